// round 5
// baseline (speedup 1.0000x reference)
#include <cuda_runtime.h>
#include <cuda_bf16.h>
#include <cstdint>

#define PAIRS 16384
#define QP    132          // fp32 tile pitch (floats)

// ---------------- smem layout (bytes) ----------------
#define SM_A_HI  0u          // 64x128 bf16 swizzled (zn, later o)
#define SM_A_LO  16384u
#define SM_B0    32768u      // one 128x128 bf16 half-image
#define SM_BALT  65536u      // borrows Q-tile space
#define SM_Q_F   16384u      // float index (byte 65536)
#define SM_K_F   24832u      // byte 99328
#define SM_V_F   33280u      // byte 133120
#define SM_G_F   41728u      // byte 166912
#define SM_ATT_F 50176u      // byte 200704, 16384 B (2 pairs x 8h x 16 x 16)
#define SMEM_TOTAL 217088u

// ---------------- W images: 5 mats x [hi 128x128][lo 128x128] bf16, [n][k] ----------------
__device__ __nv_bfloat16 g_wimg[5 * 2 * 16384];

// ---------------- helpers ----------------
__device__ __forceinline__ uint32_t smem_u32(const void* p) {
    uint32_t a;
    asm("{ .reg .u64 t; cvta.to.shared.u64 t, %1; cvt.u32.u64 %0, t; }" : "=r"(a) : "l"(p));
    return a;
}
__device__ __forceinline__ float sigmoidf_(float x) { return 1.0f / (1.0f + __expf(-x)); }

__device__ __forceinline__ void ldmA4(uint32_t r[4], uint32_t addr) {
    asm volatile("ldmatrix.sync.aligned.m8n8.x4.shared.b16 {%0,%1,%2,%3}, [%4];"
                 : "=r"(r[0]), "=r"(r[1]), "=r"(r[2]), "=r"(r[3]) : "r"(addr));
}
__device__ __forceinline__ void ldmB2(uint32_t r[2], uint32_t addr) {
    asm volatile("ldmatrix.sync.aligned.m8n8.x2.shared.b16 {%0,%1}, [%2];"
                 : "=r"(r[0]), "=r"(r[1]) : "r"(addr));
}
__device__ __forceinline__ void mma_bf16(float c[4], const uint32_t a[4], const uint32_t b[2]) {
    asm volatile(
        "mma.sync.aligned.m16n8k16.row.col.f32.bf16.bf16.f32 "
        "{%0,%1,%2,%3}, {%4,%5,%6,%7}, {%8,%9}, {%0,%1,%2,%3};"
        : "+f"(c[0]), "+f"(c[1]), "+f"(c[2]), "+f"(c[3])
        : "r"(a[0]), "r"(a[1]), "r"(a[2]), "r"(a[3]), "r"(b[0]), "r"(b[1]));
}
__device__ __forceinline__ void cp_async16(uint32_t dst, const void* src) {
    asm volatile("cp.async.ca.shared.global [%0], [%1], 16;" :: "r"(dst), "l"(src));
}
__device__ __forceinline__ void cp_commit() { asm volatile("cp.async.commit_group;"); }
#define CP_WAIT(n) asm volatile("cp.async.wait_group %0;" :: "n"(n))

// =====================================================================================
// prep: split W into bf16 hi/lo, transpose to [n][k]
// =====================================================================================
__global__ void kernel_prep(const float* __restrict__ Wq, const float* __restrict__ Wk,
                            const float* __restrict__ Wv, const float* __restrict__ Wg,
                            const float* __restrict__ Wo)
{
    const int m = blockIdx.x;
    const float* W = (m == 0) ? Wq : (m == 1) ? Wk : (m == 2) ? Wv : (m == 3) ? Wg : Wo;
    __nv_bfloat16* hi = g_wimg + (long long)m * 32768;
    __nv_bfloat16* lo = hi + 16384;
    for (int idx = threadIdx.x; idx < 16384; idx += blockDim.x) {
        const int n = idx >> 7, k = idx & 127;
        const float x = W[k * 128 + n];
        const __nv_bfloat16 h = __float2bfloat16_rn(x);
        hi[n * 128 + k] = h;
        lo[n * 128 + k] = __float2bfloat16_rn(x - __bfloat162float(h));
    }
}

// ---------------- fused-kernel building blocks ----------------
__device__ __forceinline__ void stage_half(uint32_t base, uint32_t dstOff,
                                           const __nv_bfloat16* img, int t)
{
    #pragma unroll
    for (int it = 0; it < 8; ++it) {
        const int idx = t + it * 256;
        const uint32_t row = (uint32_t)(idx >> 4), c = (uint32_t)(idx & 15);
        cp_async16(base + dstOff + row * 256u + ((c ^ (row & 7u)) << 4),
                   img + row * 128u + c * 8u);
    }
}

// one emulation pass over a staged B half. dual=true: (Ah+Al)*B, dual=false: Ah*B
__device__ __forceinline__ void gemm_half(uint32_t base, uint32_t bOff, int wm, int wn,
                                          int lane, bool dual, float c[2][4][4])
{
    const int arow0 = wm * 32 + (lane & 15);
    const int brow0 = wn * 32 + (lane & 7);
    const uint32_t asel = (uint32_t)(lane >> 4);
    const uint32_t bsel = (uint32_t)((lane >> 3) & 1);
    #pragma unroll
    for (int k = 0; k < 8; ++k) {
        uint32_t ah[2][4], al[2][4], b[4][2];
        #pragma unroll
        for (int mb = 0; mb < 2; ++mb) {
            const uint32_t row = (uint32_t)(arow0 + mb * 16);
            const uint32_t c16 = (uint32_t)(k * 2) + asel;
            const uint32_t ad = base + row * 256u + ((c16 ^ (row & 7u)) << 4);
            ldmA4(ah[mb], ad + SM_A_HI);
            if (dual) ldmA4(al[mb], ad + SM_A_LO);
        }
        #pragma unroll
        for (int nb = 0; nb < 4; ++nb) {
            const uint32_t row = (uint32_t)(brow0 + nb * 8);
            const uint32_t c16 = (uint32_t)(k * 2) + bsel;
            ldmB2(b[nb], base + bOff + row * 256u + ((c16 ^ (row & 7u)) << 4));
        }
        #pragma unroll
        for (int mb = 0; mb < 2; ++mb)
            #pragma unroll
            for (int nb = 0; nb < 4; ++nb) {
                mma_bf16(c[mb][nb], ah[mb], b[nb]);
                if (dual) mma_bf16(c[mb][nb], al[mb], b[nb]);
            }
    }
}

__device__ __forceinline__ void store_a4(char* smem, int r, int lane, float4 v)
{
    const uint32_t chunk = (uint32_t)(lane >> 1);
    const uint32_t addr = (uint32_t)r * 256u + ((chunk ^ (uint32_t)(r & 7)) << 4)
                        + (uint32_t)((lane & 1) * 8);
    __nv_bfloat162 h01, h23, l01, l23;
    const __nv_bfloat16 hx = __float2bfloat16_rn(v.x), hy = __float2bfloat16_rn(v.y);
    const __nv_bfloat16 hz = __float2bfloat16_rn(v.z), hw = __float2bfloat16_rn(v.w);
    h01.x = hx; h01.y = hy; h23.x = hz; h23.y = hw;
    l01.x = __float2bfloat16_rn(v.x - __bfloat162float(hx));
    l01.y = __float2bfloat16_rn(v.y - __bfloat162float(hy));
    l23.x = __float2bfloat16_rn(v.z - __bfloat162float(hz));
    l23.y = __float2bfloat16_rn(v.w - __bfloat162float(hw));
    *(__nv_bfloat162*)(smem + SM_A_HI + addr)     = h01;
    *(__nv_bfloat162*)(smem + SM_A_HI + addr + 4) = h23;
    *(__nv_bfloat162*)(smem + SM_A_LO + addr)     = l01;
    *(__nv_bfloat162*)(smem + SM_A_LO + addr + 4) = l23;
}

__device__ __forceinline__ void store_o2(char* smem, int r, int hc0, float x, float y)
{
    const uint32_t chunk = (uint32_t)(hc0 >> 3);
    const uint32_t addr = (uint32_t)r * 256u + ((chunk ^ (uint32_t)(r & 7)) << 4)
                        + (uint32_t)((hc0 & 7) * 2);
    const __nv_bfloat16 hx = __float2bfloat16_rn(x), hy = __float2bfloat16_rn(y);
    __nv_bfloat162 hp, lp;
    hp.x = hx; hp.y = hy;
    lp.x = __float2bfloat16_rn(x - __bfloat162float(hx));
    lp.y = __float2bfloat16_rn(y - __bfloat162float(hy));
    *(__nv_bfloat162*)(smem + SM_A_HI + addr) = hp;
    *(__nv_bfloat162*)(smem + SM_A_LO + addr) = lp;
}

__device__ __forceinline__ const __nv_bfloat16* wptr(int mat, int half) {
    return g_wimg + (long long)mat * 32768 + (long long)half * 16384;
}

// =====================================================================================
// fused: LN -> q/k/v/g GEMMs -> attention+gate (2 chunks of 2 pairs) -> out GEMM
// =====================================================================================
__global__ __launch_bounds__(256, 1)
void kernel_fused(const float* __restrict__ z,
                  const float* __restrict__ lnw, const float* __restrict__ lnb,
                  const float* __restrict__ bg,  const float* __restrict__ bo,
                  float* __restrict__ out)
{
    extern __shared__ char smem[];
    float* smf = (float*)smem;
    const uint32_t base = smem_u32(smem);

    const int t = threadIdx.x, lane = t & 31, warp = t >> 5;
    const int wm = warp >> 2, wn = warp & 3;       // 2x4 warp grid, 32x32 tiles
    const int pbase = blockIdx.x * 4;

    // ---------- LayerNorm -> zn hi/lo (swizzled A tile) ----------
    const float4 lw = *(const float4*)&lnw[lane * 4];
    const float4 lb = *(const float4*)&lnb[lane * 4];
    for (int r = warp; r < 64; r += 8) {
        const long long grow = (long long)(r & 15) * PAIRS + pbase + (r >> 4);
        const float4 zv = *(const float4*)&z[grow * 128 + lane * 4];
        float s  = zv.x + zv.y + zv.z + zv.w;
        float s2 = zv.x*zv.x + zv.y*zv.y + zv.z*zv.z + zv.w*zv.w;
        #pragma unroll
        for (int off = 16; off > 0; off >>= 1) {
            s  += __shfl_xor_sync(0xffffffffu, s,  off);
            s2 += __shfl_xor_sync(0xffffffffu, s2, off);
        }
        const float mu   = s * (1.0f / 128.0f);
        const float var  = s2 * (1.0f / 128.0f) - mu * mu;
        const float rstd = rsqrtf(var + 1e-5f);
        float4 o;
        o.x = (zv.x - mu) * rstd * lw.x + lb.x;
        o.y = (zv.y - mu) * rstd * lw.y + lb.y;
        o.z = (zv.z - mu) * rstd * lw.z + lb.z;
        o.w = (zv.w - mu) * rstd * lw.w + lb.w;
        store_a4(smem, r, lane, o);
    }
    stage_half(base, SM_B0, wptr(3, 0), t);   // Wg_hi
    cp_commit();
    __syncthreads();

    // ---------- 4 projection GEMMs, order g, v, k, q ----------
    const int ord[4] = {3, 2, 1, 0};
    const uint32_t tileF[4] = {SM_G_F, SM_V_F, SM_K_F, SM_Q_F};

    for (int s = 0; s < 4; ++s) {
        float c[2][4][4];
        #pragma unroll
        for (int i = 0; i < 2; ++i)
            #pragma unroll
            for (int j = 0; j < 4; ++j)
                #pragma unroll
                for (int q = 0; q < 4; ++q) c[i][j][q] = 0.0f;

        stage_half(base, SM_BALT, wptr(ord[s], 1), t);  // lo half
        cp_commit();
        CP_WAIT(1);
        __syncthreads();
        gemm_half(base, SM_B0, wm, wn, lane, true, c);  // Ah*Bh + Al*Bh
        __syncthreads();
        stage_half(base, SM_B0, (s < 3) ? wptr(ord[s + 1], 0) : wptr(4, 0), t); // next hi / Wo_hi
        cp_commit();
        CP_WAIT(1);
        __syncthreads();
        gemm_half(base, SM_BALT, wm, wn, lane, false, c);  // Ah*Bl
        __syncthreads();

        // epilogue -> fp32 tile (sigmoid+bg for g)
        float* tile = smf + tileF[s];
        #pragma unroll
        for (int mb = 0; mb < 2; ++mb) {
            const int r = wm * 32 + mb * 16 + (lane >> 2);
            #pragma unroll
            for (int nb = 0; nb < 4; ++nb) {
                const int col = wn * 32 + nb * 8 + 2 * (lane & 3);
                float v0 = c[mb][nb][0], v1 = c[mb][nb][1];
                float v2 = c[mb][nb][2], v3 = c[mb][nb][3];
                if (s == 0) {
                    const float b0 = bg[col], b1 = bg[col + 1];
                    v0 = sigmoidf_(v0 + b0); v1 = sigmoidf_(v1 + b1);
                    v2 = sigmoidf_(v2 + b0); v3 = sigmoidf_(v3 + b1);
                }
                *(float2*)&tile[r * QP + col]       = make_float2(v0, v1);
                *(float2*)&tile[(r + 8) * QP + col] = make_float2(v2, v3);
            }
        }
        __syncthreads();
    }

    // ---------- attention in 2 chunks of 2 pairs (att buffer = 16 KB) ----------
    for (int chunk = 0; chunk < 2; ++chunk) {
        // QK^T: 2x2 quads. e covers pl(2) x h(8) x i0(8) x j0(8) = 1024
        for (int e = t; e < 1024; e += 256) {
            const int pl = e >> 9;               // 0..1 local
            const int h  = (e >> 6) & 7;
            const int i0 = ((e >> 3) & 7) * 2;
            const int j0 = (e & 7) * 2;
            const int prow = (chunk * 2 + pl) * 16;
            const float4* q0 = (const float4*)&smf[SM_Q_F + (prow + i0) * QP + h * 16];
            const float4* q1 = (const float4*)((const float*)q0 + QP);
            const float4* k0 = (const float4*)&smf[SM_K_F + (prow + j0) * QP + h * 16];
            const float4* k1 = (const float4*)((const float*)k0 + QP);
            float s00 = 0.f, s01 = 0.f, s10 = 0.f, s11 = 0.f;
            #pragma unroll
            for (int c4 = 0; c4 < 4; ++c4) {
                const float4 a0 = q0[c4], a1 = q1[c4], b0 = k0[c4], b1 = k1[c4];
                s00 += a0.x*b0.x + a0.y*b0.y + a0.z*b0.z + a0.w*b0.w;
                s01 += a0.x*b1.x + a0.y*b1.y + a0.z*b1.z + a0.w*b1.w;
                s10 += a1.x*b0.x + a1.y*b0.y + a1.z*b0.z + a1.w*b0.w;
                s11 += a1.x*b1.x + a1.y*b1.y + a1.z*b1.z + a1.w*b1.w;
            }
            float* ab = &smf[SM_ATT_F + ((pl * 8 + h) * 16 + i0) * 16 + j0];
            ab[0]  = s00 * 0.25f; ab[1]  = s01 * 0.25f;
            ab[16] = s10 * 0.25f; ab[17] = s11 * 0.25f;
        }
        __syncthreads();

        if (chunk == 1) {
            // Q fully consumed now -> stage Wo_lo into the freed Q region (BALT)
            stage_half(base, SM_BALT, wptr(4, 1), t);
            cp_commit();
        }

        // softmax over j: 2 pairs x 8 heads x 16 i = 256 rows
        for (int rid = t; rid < 256; rid += 256) {
            float* ar = &smf[SM_ATT_F + rid * 16];
            float m = ar[0];
            #pragma unroll
            for (int j = 1; j < 16; ++j) m = fmaxf(m, ar[j]);
            float s = 0.f;
            #pragma unroll
            for (int j = 0; j < 16; ++j) { const float e_ = __expf(ar[j] - m); ar[j] = e_; s += e_; }
            const float inv = 1.0f / s;
            #pragma unroll
            for (int j = 0; j < 16; ++j) ar[j] *= inv;
        }
        __syncthreads();

        // att @ V, gate, split-store o into A tile (zn dead after projections)
        for (int e = t; e < 1024; e += 256) {
            const int pl  = e >> 9;              // 0..1 local
            const int i0  = ((e >> 6) & 7) * 2;
            const int hc0 = (e & 63) * 2;
            const float* a0 = &smf[SM_ATT_F + ((pl * 8 + (hc0 >> 4)) * 16 + i0) * 16];
            const float* a1 = a0 + 16;
            const int prow = (chunk * 2 + pl) * 16;
            const float* vb = &smf[SM_V_F + prow * QP + hc0];
            float o0x = 0.f, o0y = 0.f, o1x = 0.f, o1y = 0.f;
            #pragma unroll
            for (int j = 0; j < 16; ++j) {
                const float2 vv = *(const float2*)(vb + j * QP);
                const float w0 = a0[j], w1 = a1[j];
                o0x += w0 * vv.x; o0y += w0 * vv.y;
                o1x += w1 * vv.x; o1y += w1 * vv.y;
            }
            const int r0 = prow + i0;
            const float2 g0 = *(const float2*)&smf[SM_G_F + r0 * QP + hc0];
            const float2 g1 = *(const float2*)&smf[SM_G_F + (r0 + 1) * QP + hc0];
            store_o2(smem, r0,     hc0, o0x * g0.x, o0y * g0.y);
            store_o2(smem, r0 + 1, hc0, o1x * g1.x, o1y * g1.y);
        }
        __syncthreads();   // att buffer reused by next chunk
    }

    // ---------- out GEMM: o @ Wo + bo ----------
    {
        float c[2][4][4];
        #pragma unroll
        for (int i = 0; i < 2; ++i)
            #pragma unroll
            for (int j = 0; j < 4; ++j)
                #pragma unroll
                for (int q = 0; q < 4; ++q) c[i][j][q] = 0.0f;

        CP_WAIT(1);          // Wo_hi landed
        __syncthreads();
        gemm_half(base, SM_B0, wm, wn, lane, true, c);
        CP_WAIT(0);          // Wo_lo landed
        __syncthreads();
        gemm_half(base, SM_BALT, wm, wn, lane, false, c);

        #pragma unroll
        for (int mb = 0; mb < 2; ++mb) {
            const int r = wm * 32 + mb * 16 + (lane >> 2);
            const long long grow  = (long long)(r & 15) * PAIRS + pbase + (r >> 4);
            const int r8 = r + 8;
            const long long grow8 = (long long)(r8 & 15) * PAIRS + pbase + (r8 >> 4);
            #pragma unroll
            for (int nb = 0; nb < 4; ++nb) {
                const int col = wn * 32 + nb * 8 + 2 * (lane & 3);
                const float b0 = bo[col], b1 = bo[col + 1];
                *(float2*)&out[grow  * 128 + col] = make_float2(c[mb][nb][0] + b0, c[mb][nb][1] + b1);
                *(float2*)&out[grow8 * 128 + col] = make_float2(c[mb][nb][2] + b0, c[mb][nb][3] + b1);
            }
        }
    }
}

// =====================================================================================
extern "C" void kernel_launch(void* const* d_in, const int* in_sizes, int n_in,
                              void* d_out, int out_size)
{
    (void)in_sizes; (void)n_in; (void)out_size;
    const float* z   = (const float*)d_in[0];
    const float* lnw = (const float*)d_in[1];
    const float* lnb = (const float*)d_in[2];
    const float* Wq  = (const float*)d_in[3];
    const float* Wk  = (const float*)d_in[4];
    const float* Wv  = (const float*)d_in[5];
    const float* Wg  = (const float*)d_in[6];
    const float* bg  = (const float*)d_in[7];
    const float* Wo  = (const float*)d_in[8];
    const float* bo  = (const float*)d_in[9];
    float* out = (float*)d_out;

    cudaFuncSetAttribute(kernel_fused, cudaFuncAttributeMaxDynamicSharedMemorySize, SMEM_TOTAL);

    kernel_prep<<<5, 256>>>(Wq, Wk, Wv, Wg, Wo);
    kernel_fused<<<4096, 256, SMEM_TOTAL>>>(z, lnw, lnb, bg, bo, out);
}

// round 6
// speedup vs baseline: 1.0829x; 1.0829x over previous
#include <cuda_runtime.h>
#include <cuda_bf16.h>
#include <cstdint>

#define PAIRS 16384
#define QP    132          // fp32 tile pitch (floats)

// ---------------- smem layout (bytes) ----------------
#define SM_A_HI  0u          // 64x128 bf16 swizzled (zn, later o)
#define SM_A_LO  16384u
#define SM_B0    32768u      // one 128x128 bf16 half-image
#define SM_BALT  65536u      // borrows Q-tile space
#define SM_Q_F   16384u      // float index (byte 65536)
#define SM_K_F   24832u      // byte 99328
#define SM_V_F   33280u      // byte 133120
#define SM_G_F   41728u      // byte 166912
#define SM_ATT_F 50176u      // byte 200704, 16384 B (2 pairs x 8h x 16 x 16)
#define SMEM_TOTAL 217088u

#define NT 512               // threads per CTA (16 warps)

// ---------------- W images: 5 mats x [hi 128x128][lo 128x128] bf16, [n][k] ----------------
__device__ __nv_bfloat16 g_wimg[5 * 2 * 16384];

// ---------------- helpers ----------------
__device__ __forceinline__ uint32_t smem_u32(const void* p) {
    uint32_t a;
    asm("{ .reg .u64 t; cvta.to.shared.u64 t, %1; cvt.u32.u64 %0, t; }" : "=r"(a) : "l"(p));
    return a;
}
__device__ __forceinline__ float sigmoidf_(float x) { return 1.0f / (1.0f + __expf(-x)); }

__device__ __forceinline__ void ldmA4(uint32_t r[4], uint32_t addr) {
    asm volatile("ldmatrix.sync.aligned.m8n8.x4.shared.b16 {%0,%1,%2,%3}, [%4];"
                 : "=r"(r[0]), "=r"(r[1]), "=r"(r[2]), "=r"(r[3]) : "r"(addr));
}
__device__ __forceinline__ void ldmB2(uint32_t r[2], uint32_t addr) {
    asm volatile("ldmatrix.sync.aligned.m8n8.x2.shared.b16 {%0,%1}, [%2];"
                 : "=r"(r[0]), "=r"(r[1]) : "r"(addr));
}
__device__ __forceinline__ void mma_bf16(float c[4], const uint32_t a[4], const uint32_t b[2]) {
    asm volatile(
        "mma.sync.aligned.m16n8k16.row.col.f32.bf16.bf16.f32 "
        "{%0,%1,%2,%3}, {%4,%5,%6,%7}, {%8,%9}, {%0,%1,%2,%3};"
        : "+f"(c[0]), "+f"(c[1]), "+f"(c[2]), "+f"(c[3])
        : "r"(a[0]), "r"(a[1]), "r"(a[2]), "r"(a[3]), "r"(b[0]), "r"(b[1]));
}
__device__ __forceinline__ void cp_async16(uint32_t dst, const void* src) {
    asm volatile("cp.async.ca.shared.global [%0], [%1], 16;" :: "r"(dst), "l"(src));
}
__device__ __forceinline__ void cp_commit() { asm volatile("cp.async.commit_group;"); }
#define CP_WAIT(n) asm volatile("cp.async.wait_group %0;" :: "n"(n))

// =====================================================================================
// prep: split W into bf16 hi/lo, transpose to [n][k]
// =====================================================================================
__global__ void kernel_prep(const float* __restrict__ Wq, const float* __restrict__ Wk,
                            const float* __restrict__ Wv, const float* __restrict__ Wg,
                            const float* __restrict__ Wo)
{
    const int m = blockIdx.x;
    const float* W = (m == 0) ? Wq : (m == 1) ? Wk : (m == 2) ? Wv : (m == 3) ? Wg : Wo;
    __nv_bfloat16* hi = g_wimg + (long long)m * 32768;
    __nv_bfloat16* lo = hi + 16384;
    for (int idx = threadIdx.x; idx < 16384; idx += blockDim.x) {
        const int n = idx >> 7, k = idx & 127;
        const float x = W[k * 128 + n];
        const __nv_bfloat16 h = __float2bfloat16_rn(x);
        hi[n * 128 + k] = h;
        lo[n * 128 + k] = __float2bfloat16_rn(x - __bfloat162float(h));
    }
}

// ---------------- fused-kernel building blocks ----------------
__device__ __forceinline__ void stage_half(uint32_t base, uint32_t dstOff,
                                           const __nv_bfloat16* img, int t)
{
    #pragma unroll
    for (int it = 0; it < 4; ++it) {
        const int idx = t + it * NT;
        const uint32_t row = (uint32_t)(idx >> 4), c = (uint32_t)(idx & 15);
        cp_async16(base + dstOff + row * 256u + ((c ^ (row & 7u)) << 4),
                   img + row * 128u + c * 8u);
    }
}

// one emulation pass over a staged B half. dual=true: (Ah+Al)*B, dual=false: Ah*B
// 16-warp version: each warp owns a 16x32 output tile (wm 0..3, wn 0..3)
__device__ __forceinline__ void gemm_half(uint32_t base, uint32_t bOff, int wm, int wn,
                                          int lane, bool dual, float c[4][4])
{
    const int arow0 = wm * 16 + (lane & 15);
    const int brow0 = wn * 32 + (lane & 7);
    const uint32_t asel = (uint32_t)(lane >> 4);
    const uint32_t bsel = (uint32_t)((lane >> 3) & 1);
    #pragma unroll
    for (int k = 0; k < 8; ++k) {
        uint32_t ah[4], al[4], b[4][2];
        {
            const uint32_t row = (uint32_t)arow0;
            const uint32_t c16 = (uint32_t)(k * 2) + asel;
            const uint32_t ad = base + row * 256u + ((c16 ^ (row & 7u)) << 4);
            ldmA4(ah, ad + SM_A_HI);
            if (dual) ldmA4(al, ad + SM_A_LO);
        }
        #pragma unroll
        for (int nb = 0; nb < 4; ++nb) {
            const uint32_t row = (uint32_t)(brow0 + nb * 8);
            const uint32_t c16 = (uint32_t)(k * 2) + bsel;
            ldmB2(b[nb], base + bOff + row * 256u + ((c16 ^ (row & 7u)) << 4));
        }
        #pragma unroll
        for (int nb = 0; nb < 4; ++nb) {
            mma_bf16(c[nb], ah, b[nb]);
            if (dual) mma_bf16(c[nb], al, b[nb]);
        }
    }
}

__device__ __forceinline__ void store_a4(char* smem, int r, int lane, float4 v)
{
    const uint32_t chunk = (uint32_t)(lane >> 1);
    const uint32_t addr = (uint32_t)r * 256u + ((chunk ^ (uint32_t)(r & 7)) << 4)
                        + (uint32_t)((lane & 1) * 8);
    __nv_bfloat162 h01, h23, l01, l23;
    const __nv_bfloat16 hx = __float2bfloat16_rn(v.x), hy = __float2bfloat16_rn(v.y);
    const __nv_bfloat16 hz = __float2bfloat16_rn(v.z), hw = __float2bfloat16_rn(v.w);
    h01.x = hx; h01.y = hy; h23.x = hz; h23.y = hw;
    l01.x = __float2bfloat16_rn(v.x - __bfloat162float(hx));
    l01.y = __float2bfloat16_rn(v.y - __bfloat162float(hy));
    l23.x = __float2bfloat16_rn(v.z - __bfloat162float(hz));
    l23.y = __float2bfloat16_rn(v.w - __bfloat162float(hw));
    *(__nv_bfloat162*)(smem + SM_A_HI + addr)     = h01;
    *(__nv_bfloat162*)(smem + SM_A_HI + addr + 4) = h23;
    *(__nv_bfloat162*)(smem + SM_A_LO + addr)     = l01;
    *(__nv_bfloat162*)(smem + SM_A_LO + addr + 4) = l23;
}

__device__ __forceinline__ void store_o2(char* smem, int r, int hc0, float x, float y)
{
    const uint32_t chunk = (uint32_t)(hc0 >> 3);
    const uint32_t addr = (uint32_t)r * 256u + ((chunk ^ (uint32_t)(r & 7)) << 4)
                        + (uint32_t)((hc0 & 7) * 2);
    const __nv_bfloat16 hx = __float2bfloat16_rn(x), hy = __float2bfloat16_rn(y);
    __nv_bfloat162 hp, lp;
    hp.x = hx; hp.y = hy;
    lp.x = __float2bfloat16_rn(x - __bfloat162float(hx));
    lp.y = __float2bfloat16_rn(y - __bfloat162float(hy));
    *(__nv_bfloat162*)(smem + SM_A_HI + addr) = hp;
    *(__nv_bfloat162*)(smem + SM_A_LO + addr) = lp;
}

__device__ __forceinline__ const __nv_bfloat16* wptr(int mat, int half) {
    return g_wimg + (long long)mat * 32768 + (long long)half * 16384;
}

// =====================================================================================
// fused: LN -> q/k/v/g GEMMs -> attention+gate (2 chunks of 2 pairs) -> out GEMM
// 512 threads / 16 warps for latency hiding
// =====================================================================================
__global__ __launch_bounds__(NT, 1)
void kernel_fused(const float* __restrict__ z,
                  const float* __restrict__ lnw, const float* __restrict__ lnb,
                  const float* __restrict__ bg,  const float* __restrict__ bo,
                  float* __restrict__ out)
{
    extern __shared__ char smem[];
    float* smf = (float*)smem;
    const uint32_t base = smem_u32(smem);

    const int t = threadIdx.x, lane = t & 31, warp = t >> 5;
    const int wm = warp >> 2, wn = warp & 3;       // 4x4 warp grid, 16x32 tiles
    const int pbase = blockIdx.x * 4;

    // ---------- LayerNorm -> zn hi/lo (swizzled A tile) ----------
    const float4 lw = *(const float4*)&lnw[lane * 4];
    const float4 lb = *(const float4*)&lnb[lane * 4];
    for (int r = warp; r < 64; r += 16) {
        const long long grow = (long long)(r & 15) * PAIRS + pbase + (r >> 4);
        const float4 zv = *(const float4*)&z[grow * 128 + lane * 4];
        float s  = zv.x + zv.y + zv.z + zv.w;
        float s2 = zv.x*zv.x + zv.y*zv.y + zv.z*zv.z + zv.w*zv.w;
        #pragma unroll
        for (int off = 16; off > 0; off >>= 1) {
            s  += __shfl_xor_sync(0xffffffffu, s,  off);
            s2 += __shfl_xor_sync(0xffffffffu, s2, off);
        }
        const float mu   = s * (1.0f / 128.0f);
        const float var  = s2 * (1.0f / 128.0f) - mu * mu;
        const float rstd = rsqrtf(var + 1e-5f);
        float4 o;
        o.x = (zv.x - mu) * rstd * lw.x + lb.x;
        o.y = (zv.y - mu) * rstd * lw.y + lb.y;
        o.z = (zv.z - mu) * rstd * lw.z + lb.z;
        o.w = (zv.w - mu) * rstd * lw.w + lb.w;
        store_a4(smem, r, lane, o);
    }
    stage_half(base, SM_B0, wptr(3, 0), t);   // Wg_hi
    cp_commit();
    __syncthreads();

    // ---------- 4 projection GEMMs, order g, v, k, q ----------
    const int ord[4] = {3, 2, 1, 0};
    const uint32_t tileF[4] = {SM_G_F, SM_V_F, SM_K_F, SM_Q_F};

    for (int s = 0; s < 4; ++s) {
        float c[4][4];
        #pragma unroll
        for (int j = 0; j < 4; ++j)
            #pragma unroll
            for (int q = 0; q < 4; ++q) c[j][q] = 0.0f;

        stage_half(base, SM_BALT, wptr(ord[s], 1), t);  // lo half
        cp_commit();
        CP_WAIT(1);
        __syncthreads();
        gemm_half(base, SM_B0, wm, wn, lane, true, c);  // Ah*Bh + Al*Bh
        __syncthreads();
        stage_half(base, SM_B0, (s < 3) ? wptr(ord[s + 1], 0) : wptr(4, 0), t); // next hi / Wo_hi
        cp_commit();
        CP_WAIT(1);
        __syncthreads();
        gemm_half(base, SM_BALT, wm, wn, lane, false, c);  // Ah*Bl
        __syncthreads();

        // epilogue -> fp32 tile (sigmoid+bg for g)
        float* tile = smf + tileF[s];
        const int r = wm * 16 + (lane >> 2);
        #pragma unroll
        for (int nb = 0; nb < 4; ++nb) {
            const int col = wn * 32 + nb * 8 + 2 * (lane & 3);
            float v0 = c[nb][0], v1 = c[nb][1];
            float v2 = c[nb][2], v3 = c[nb][3];
            if (s == 0) {
                const float b0 = bg[col], b1 = bg[col + 1];
                v0 = sigmoidf_(v0 + b0); v1 = sigmoidf_(v1 + b1);
                v2 = sigmoidf_(v2 + b0); v3 = sigmoidf_(v3 + b1);
            }
            *(float2*)&tile[r * QP + col]       = make_float2(v0, v1);
            *(float2*)&tile[(r + 8) * QP + col] = make_float2(v2, v3);
        }
        __syncthreads();
    }

    // ---------- attention in 2 chunks of 2 pairs (att buffer = 16 KB) ----------
    for (int chunk = 0; chunk < 2; ++chunk) {
        // QK^T: 2x2 quads. e covers pl(2) x h(8) x i0(8) x j0(8) = 1024
        for (int e = t; e < 1024; e += NT) {
            const int pl = e >> 9;               // 0..1 local
            const int h  = (e >> 6) & 7;
            const int i0 = ((e >> 3) & 7) * 2;
            const int j0 = (e & 7) * 2;
            const int prow = (chunk * 2 + pl) * 16;
            const float4* q0 = (const float4*)&smf[SM_Q_F + (prow + i0) * QP + h * 16];
            const float4* q1 = (const float4*)((const float*)q0 + QP);
            const float4* k0 = (const float4*)&smf[SM_K_F + (prow + j0) * QP + h * 16];
            const float4* k1 = (const float4*)((const float*)k0 + QP);
            float s00 = 0.f, s01 = 0.f, s10 = 0.f, s11 = 0.f;
            #pragma unroll
            for (int c4 = 0; c4 < 4; ++c4) {
                const float4 a0 = q0[c4], a1 = q1[c4], b0 = k0[c4], b1 = k1[c4];
                s00 += a0.x*b0.x + a0.y*b0.y + a0.z*b0.z + a0.w*b0.w;
                s01 += a0.x*b1.x + a0.y*b1.y + a0.z*b1.z + a0.w*b1.w;
                s10 += a1.x*b0.x + a1.y*b0.y + a1.z*b0.z + a1.w*b0.w;
                s11 += a1.x*b1.x + a1.y*b1.y + a1.z*b1.z + a1.w*b1.w;
            }
            float* ab = &smf[SM_ATT_F + ((pl * 8 + h) * 16 + i0) * 16 + j0];
            ab[0]  = s00 * 0.25f; ab[1]  = s01 * 0.25f;
            ab[16] = s10 * 0.25f; ab[17] = s11 * 0.25f;
        }
        __syncthreads();

        if (chunk == 1) {
            // Q fully consumed now -> stage Wo_lo into the freed Q region (BALT)
            stage_half(base, SM_BALT, wptr(4, 1), t);
            cp_commit();
        }

        // softmax over j: 2 pairs x 8 heads x 16 i = 256 rows
        if (t < 256) {
            float* ar = &smf[SM_ATT_F + t * 16];
            float m = ar[0];
            #pragma unroll
            for (int j = 1; j < 16; ++j) m = fmaxf(m, ar[j]);
            float s = 0.f;
            #pragma unroll
            for (int j = 0; j < 16; ++j) { const float e_ = __expf(ar[j] - m); ar[j] = e_; s += e_; }
            const float inv = 1.0f / s;
            #pragma unroll
            for (int j = 0; j < 16; ++j) ar[j] *= inv;
        }
        __syncthreads();

        // att @ V, gate, split-store o into A tile (zn dead after projections)
        for (int e = t; e < 1024; e += NT) {
            const int pl  = e >> 9;              // 0..1 local
            const int i0  = ((e >> 6) & 7) * 2;
            const int hc0 = (e & 63) * 2;
            const float* a0 = &smf[SM_ATT_F + ((pl * 8 + (hc0 >> 4)) * 16 + i0) * 16];
            const float* a1 = a0 + 16;
            const int prow = (chunk * 2 + pl) * 16;
            const float* vb = &smf[SM_V_F + prow * QP + hc0];
            float o0x = 0.f, o0y = 0.f, o1x = 0.f, o1y = 0.f;
            #pragma unroll
            for (int j = 0; j < 16; ++j) {
                const float2 vv = *(const float2*)(vb + j * QP);
                const float w0 = a0[j], w1 = a1[j];
                o0x += w0 * vv.x; o0y += w0 * vv.y;
                o1x += w1 * vv.x; o1y += w1 * vv.y;
            }
            const int r0 = prow + i0;
            const float2 g0 = *(const float2*)&smf[SM_G_F + r0 * QP + hc0];
            const float2 g1 = *(const float2*)&smf[SM_G_F + (r0 + 1) * QP + hc0];
            store_o2(smem, r0,     hc0, o0x * g0.x, o0y * g0.y);
            store_o2(smem, r0 + 1, hc0, o1x * g1.x, o1y * g1.y);
        }
        __syncthreads();   // att buffer reused by next chunk
    }

    // ---------- out GEMM: o @ Wo + bo ----------
    {
        float c[4][4];
        #pragma unroll
        for (int j = 0; j < 4; ++j)
            #pragma unroll
            for (int q = 0; q < 4; ++q) c[j][q] = 0.0f;

        CP_WAIT(1);          // Wo_hi landed
        __syncthreads();
        gemm_half(base, SM_B0, wm, wn, lane, true, c);
        CP_WAIT(0);          // Wo_lo landed
        __syncthreads();
        gemm_half(base, SM_BALT, wm, wn, lane, false, c);

        const int r  = wm * 16 + (lane >> 2);
        const int r8 = r + 8;
        const long long grow  = (long long)(r  & 15) * PAIRS + pbase + (r  >> 4);
        const long long grow8 = (long long)(r8 & 15) * PAIRS + pbase + (r8 >> 4);
        #pragma unroll
        for (int nb = 0; nb < 4; ++nb) {
            const int col = wn * 32 + nb * 8 + 2 * (lane & 3);
            const float b0 = bo[col], b1 = bo[col + 1];
            *(float2*)&out[grow  * 128 + col] = make_float2(c[nb][0] + b0, c[nb][1] + b1);
            *(float2*)&out[grow8 * 128 + col] = make_float2(c[nb][2] + b0, c[nb][3] + b1);
        }
    }
}

// =====================================================================================
extern "C" void kernel_launch(void* const* d_in, const int* in_sizes, int n_in,
                              void* d_out, int out_size)
{
    (void)in_sizes; (void)n_in; (void)out_size;
    const float* z   = (const float*)d_in[0];
    const float* lnw = (const float*)d_in[1];
    const float* lnb = (const float*)d_in[2];
    const float* Wq  = (const float*)d_in[3];
    const float* Wk  = (const float*)d_in[4];
    const float* Wv  = (const float*)d_in[5];
    const float* Wg  = (const float*)d_in[6];
    const float* bg  = (const float*)d_in[7];
    const float* Wo  = (const float*)d_in[8];
    const float* bo  = (const float*)d_in[9];
    float* out = (float*)d_out;

    cudaFuncSetAttribute(kernel_fused, cudaFuncAttributeMaxDynamicSharedMemorySize, SMEM_TOTAL);

    kernel_prep<<<5, 256>>>(Wq, Wk, Wv, Wg, Wo);
    kernel_fused<<<4096, NT, SMEM_TOTAL>>>(z, lnw, lnb, bg, bo, out);
}

// round 7
// speedup vs baseline: 1.4484x; 1.3375x over previous
#include <cuda_runtime.h>
#include <cuda_fp16.h>
#include <cstdint>

#define PAIRS 16384
#define QP    132          // fp32 tile pitch (floats)

// ---------------- smem layout (bytes) ----------------
#define SM_A_HI  0u          // 64x128 fp16 swizzled (zn, later o)
#define SM_A_LO  16384u
#define SM_B0    32768u      // one 128x128 fp16 W image (32KB)
#define SM_BALT  65536u      // borrows Q-tile space (32KB)
#define SM_Q_F   16384u      // float index (byte 65536)
#define SM_K_F   24832u      // byte 99328
#define SM_V_F   33280u      // byte 133120
#define SM_G_F   41728u      // byte 166912
#define SM_ATT_F 50176u      // byte 200704, 16384 B (2 pairs x 8h x 16 x 16)
#define SMEM_TOTAL 217088u

#define NT 512               // threads per CTA (16 warps)

// ---------------- W images: 5 mats x 128x128 fp16 (hi only), [n][k] ----------------
__device__ __half g_wimg[5 * 16384];

// ---------------- helpers ----------------
__device__ __forceinline__ uint32_t smem_u32(const void* p) {
    uint32_t a;
    asm("{ .reg .u64 t; cvta.to.shared.u64 t, %1; cvt.u32.u64 %0, t; }" : "=r"(a) : "l"(p));
    return a;
}
__device__ __forceinline__ float sigmoidf_(float x) { return 1.0f / (1.0f + __expf(-x)); }

__device__ __forceinline__ void ldmA4(uint32_t r[4], uint32_t addr) {
    asm volatile("ldmatrix.sync.aligned.m8n8.x4.shared.b16 {%0,%1,%2,%3}, [%4];"
                 : "=r"(r[0]), "=r"(r[1]), "=r"(r[2]), "=r"(r[3]) : "r"(addr));
}
__device__ __forceinline__ void ldmB2(uint32_t r[2], uint32_t addr) {
    asm volatile("ldmatrix.sync.aligned.m8n8.x2.shared.b16 {%0,%1}, [%2];"
                 : "=r"(r[0]), "=r"(r[1]) : "r"(addr));
}
__device__ __forceinline__ void mma_f16(float c[4], const uint32_t a[4], const uint32_t b[2]) {
    asm volatile(
        "mma.sync.aligned.m16n8k16.row.col.f32.f16.f16.f32 "
        "{%0,%1,%2,%3}, {%4,%5,%6,%7}, {%8,%9}, {%0,%1,%2,%3};"
        : "+f"(c[0]), "+f"(c[1]), "+f"(c[2]), "+f"(c[3])
        : "r"(a[0]), "r"(a[1]), "r"(a[2]), "r"(a[3]), "r"(b[0]), "r"(b[1]));
}
__device__ __forceinline__ void cp_async16(uint32_t dst, const void* src) {
    asm volatile("cp.async.ca.shared.global [%0], [%1], 16;" :: "r"(dst), "l"(src));
}
__device__ __forceinline__ void cp_commit() { asm volatile("cp.async.commit_group;"); }
#define CP_WAIT(n) asm volatile("cp.async.wait_group %0;" :: "n"(n))

// =====================================================================================
// prep: round W to fp16, transpose to [n][k]
// =====================================================================================
__global__ void kernel_prep(const float* __restrict__ Wq, const float* __restrict__ Wk,
                            const float* __restrict__ Wv, const float* __restrict__ Wg,
                            const float* __restrict__ Wo)
{
    const int m = blockIdx.x;
    const float* W = (m == 0) ? Wq : (m == 1) ? Wk : (m == 2) ? Wv : (m == 3) ? Wg : Wo;
    __half* hi = g_wimg + (long long)m * 16384;
    for (int idx = threadIdx.x; idx < 16384; idx += blockDim.x) {
        const int n = idx >> 7, k = idx & 127;
        hi[n * 128 + k] = __float2half_rn(W[k * 128 + n]);
    }
}

// ---------------- fused-kernel building blocks ----------------
// stage one 128x128 fp16 image (32KB) into a swizzled smem tile via cp.async
__device__ __forceinline__ void stage_img(uint32_t base, uint32_t dstOff,
                                          const __half* img, int t)
{
    #pragma unroll
    for (int it = 0; it < 4; ++it) {
        const int idx = t + it * NT;
        const uint32_t row = (uint32_t)(idx >> 4), c = (uint32_t)(idx & 15);
        cp_async16(base + dstOff + row * 256u + ((c ^ (row & 7u)) << 4),
                   img + row * 128u + c * 8u);
    }
}

// dual pass: C += Ah*B + Al*B  (exactly A_fp32 * B_fp16)
// 16 warps: each warp owns a 16x32 output tile (wm 0..3, wn 0..3)
__device__ __forceinline__ void gemm_dual(uint32_t base, uint32_t bOff, int wm, int wn,
                                          int lane, float c[4][4])
{
    const uint32_t arow = (uint32_t)(wm * 16 + (lane & 15));
    const uint32_t asel = (uint32_t)(lane >> 4);
    const int brow0 = wn * 32 + (lane & 7);
    const uint32_t bsel = (uint32_t)((lane >> 3) & 1);
    #pragma unroll
    for (int k = 0; k < 8; ++k) {
        uint32_t ah[4], al[4], b[4][2];
        const uint32_t c16 = (uint32_t)(k * 2) + asel;
        const uint32_t ad = base + arow * 256u + ((c16 ^ (arow & 7u)) << 4);
        ldmA4(ah, ad + SM_A_HI);
        ldmA4(al, ad + SM_A_LO);
        #pragma unroll
        for (int nb = 0; nb < 4; ++nb) {
            const uint32_t row = (uint32_t)(brow0 + nb * 8);
            const uint32_t bc = (uint32_t)(k * 2) + bsel;
            ldmB2(b[nb], base + bOff + row * 256u + ((bc ^ (row & 7u)) << 4));
        }
        #pragma unroll
        for (int nb = 0; nb < 4; ++nb) {
            mma_f16(c[nb], ah, b[nb]);
            mma_f16(c[nb], al, b[nb]);
        }
    }
}

// split 4 floats -> hi/lo fp16, store 8B each into swizzled A tile
__device__ __forceinline__ void store_a4(char* smem, int r, int lane, float4 v)
{
    const uint32_t chunk = (uint32_t)(lane >> 1);
    const uint32_t addr = (uint32_t)r * 256u + ((chunk ^ (uint32_t)(r & 7)) << 4)
                        + (uint32_t)((lane & 1) * 8);
    const __half hx = __float2half_rn(v.x), hy = __float2half_rn(v.y);
    const __half hz = __float2half_rn(v.z), hw = __float2half_rn(v.w);
    const __half2 h01 = __halves2half2(hx, hy), h23 = __halves2half2(hz, hw);
    const __half2 l01 = __halves2half2(__float2half_rn(v.x - __half2float(hx)),
                                       __float2half_rn(v.y - __half2float(hy)));
    const __half2 l23 = __halves2half2(__float2half_rn(v.z - __half2float(hz)),
                                       __float2half_rn(v.w - __half2float(hw)));
    *(__half2*)(smem + SM_A_HI + addr)     = h01;
    *(__half2*)(smem + SM_A_HI + addr + 4) = h23;
    *(__half2*)(smem + SM_A_LO + addr)     = l01;
    *(__half2*)(smem + SM_A_LO + addr + 4) = l23;
}

__device__ __forceinline__ void store_o2(char* smem, int r, int hc0, float x, float y)
{
    const uint32_t chunk = (uint32_t)(hc0 >> 3);
    const uint32_t addr = (uint32_t)r * 256u + ((chunk ^ (uint32_t)(r & 7)) << 4)
                        + (uint32_t)((hc0 & 7) * 2);
    const __half hx = __float2half_rn(x), hy = __float2half_rn(y);
    const __half2 hp = __halves2half2(hx, hy);
    const __half2 lp = __halves2half2(__float2half_rn(x - __half2float(hx)),
                                      __float2half_rn(y - __half2float(hy)));
    *(__half2*)(smem + SM_A_HI + addr) = hp;
    *(__half2*)(smem + SM_A_LO + addr) = lp;
}

__device__ __forceinline__ const __half* wimg(int mat) {
    return g_wimg + (long long)mat * 16384;
}

// =====================================================================================
// fused: LN -> q/k/v/g GEMMs -> attention+gate (2 chunks of 2 pairs) -> out GEMM
// =====================================================================================
__global__ __launch_bounds__(NT, 1)
void kernel_fused(const float* __restrict__ z,
                  const float* __restrict__ lnw, const float* __restrict__ lnb,
                  const float* __restrict__ bg,  const float* __restrict__ bo,
                  float* __restrict__ out)
{
    extern __shared__ char smem[];
    float* smf = (float*)smem;
    const uint32_t base = smem_u32(smem);

    const int t = threadIdx.x, lane = t & 31, warp = t >> 5;
    const int wm = warp >> 2, wn = warp & 3;       // 4x4 warp grid, 16x32 tiles
    const int pbase = blockIdx.x * 4;

    // ---------- LayerNorm -> zn hi/lo (swizzled A tile) ----------
    const float4 lw = *(const float4*)&lnw[lane * 4];
    const float4 lb = *(const float4*)&lnb[lane * 4];
    for (int r = warp; r < 64; r += 16) {
        const long long grow = (long long)(r & 15) * PAIRS + pbase + (r >> 4);
        const float4 zv = *(const float4*)&z[grow * 128 + lane * 4];
        float s  = zv.x + zv.y + zv.z + zv.w;
        float s2 = zv.x*zv.x + zv.y*zv.y + zv.z*zv.z + zv.w*zv.w;
        #pragma unroll
        for (int off = 16; off > 0; off >>= 1) {
            s  += __shfl_xor_sync(0xffffffffu, s,  off);
            s2 += __shfl_xor_sync(0xffffffffu, s2, off);
        }
        const float mu   = s * (1.0f / 128.0f);
        const float var  = s2 * (1.0f / 128.0f) - mu * mu;
        const float rstd = rsqrtf(var + 1e-5f);
        float4 o;
        o.x = (zv.x - mu) * rstd * lw.x + lb.x;
        o.y = (zv.y - mu) * rstd * lw.y + lb.y;
        o.z = (zv.z - mu) * rstd * lw.z + lb.z;
        o.w = (zv.w - mu) * rstd * lw.w + lb.w;
        store_a4(smem, r, lane, o);
    }
    stage_img(base, SM_B0, wimg(3), t);   // Wg
    cp_commit();
    CP_WAIT(0);
    __syncthreads();

    // ---------- 4 projection GEMMs, order g, v, k, q ----------
    const int ord[4] = {3, 2, 1, 0};
    const uint32_t tileF[4] = {SM_G_F, SM_V_F, SM_K_F, SM_Q_F};

    for (int s = 0; s < 4; ++s) {
        const uint32_t buf   = (s & 1) ? SM_BALT : SM_B0;
        const uint32_t other = (s & 1) ? SM_B0   : SM_BALT;
        // prefetch next image (Wo for s==3) into the buffer not being read
        stage_img(base, other, wimg((s < 3) ? ord[s + 1] : 4), t);
        cp_commit();

        float c[4][4];
        #pragma unroll
        for (int j = 0; j < 4; ++j)
            #pragma unroll
            for (int q = 0; q < 4; ++q) c[j][q] = 0.0f;

        gemm_dual(base, buf, wm, wn, lane, c);
        __syncthreads();   // gemm reads done before epilogue overwrites Q region (s==3)

        // epilogue -> fp32 tile (sigmoid+bg for g)
        float* tile = smf + tileF[s];
        const int r = wm * 16 + (lane >> 2);
        #pragma unroll
        for (int nb = 0; nb < 4; ++nb) {
            const int col = wn * 32 + nb * 8 + 2 * (lane & 3);
            float v0 = c[nb][0], v1 = c[nb][1];
            float v2 = c[nb][2], v3 = c[nb][3];
            if (s == 0) {
                const float b0 = bg[col], b1 = bg[col + 1];
                v0 = sigmoidf_(v0 + b0); v1 = sigmoidf_(v1 + b1);
                v2 = sigmoidf_(v2 + b0); v3 = sigmoidf_(v3 + b1);
            }
            *(float2*)&tile[r * QP + col]       = make_float2(v0, v1);
            *(float2*)&tile[(r + 8) * QP + col] = make_float2(v2, v3);
        }
        CP_WAIT(0);        // next image staged
        __syncthreads();   // visible to all; epilogue tile visible
    }

    // ---------- attention in 2 chunks of 2 pairs (att buffer = 16 KB) ----------
    for (int chunk = 0; chunk < 2; ++chunk) {
        // QK^T: 4x2 blocking. 512 units: pl(2) x h(8) x iblk(4) x jblk(8)
        {
            const int e  = t;
            const int pl = e >> 8;
            const int h  = (e >> 5) & 7;
            const int i0 = ((e >> 3) & 3) * 4;
            const int j0 = (e & 7) * 2;
            const int prow = (chunk * 2 + pl) * 16;
            const float* qb = &smf[SM_Q_F + (prow + i0) * QP + h * 16];
            const float* kb = &smf[SM_K_F + (prow + j0) * QP + h * 16];
            float s[4][2] = {};
            #pragma unroll
            for (int c4 = 0; c4 < 4; ++c4) {
                const float4 k0 = *(const float4*)(kb + c4 * 4);
                const float4 k1 = *(const float4*)(kb + QP + c4 * 4);
                #pragma unroll
                for (int i = 0; i < 4; ++i) {
                    const float4 q = *(const float4*)(qb + i * QP + c4 * 4);
                    s[i][0] += q.x*k0.x + q.y*k0.y + q.z*k0.z + q.w*k0.w;
                    s[i][1] += q.x*k1.x + q.y*k1.y + q.z*k1.z + q.w*k1.w;
                }
            }
            #pragma unroll
            for (int i = 0; i < 4; ++i) {
                float* ab = &smf[SM_ATT_F + ((pl * 8 + h) * 16 + i0 + i) * 16 + j0];
                ab[0] = s[i][0] * 0.25f;
                ab[1] = s[i][1] * 0.25f;
            }
        }
        __syncthreads();

        // softmax over j: 2 pairs x 8 heads x 16 i = 256 rows
        if (t < 256) {
            float* ar = &smf[SM_ATT_F + t * 16];
            float m = ar[0];
            #pragma unroll
            for (int j = 1; j < 16; ++j) m = fmaxf(m, ar[j]);
            float s = 0.f;
            #pragma unroll
            for (int j = 0; j < 16; ++j) { const float e_ = __expf(ar[j] - m); ar[j] = e_; s += e_; }
            const float inv = 1.0f / s;
            #pragma unroll
            for (int j = 0; j < 16; ++j) ar[j] *= inv;
        }
        __syncthreads();

        // att @ V, gate, split-store o into A tile. 512 units: pl(2) x iblk(4) x hcblk(64)
        {
            const int e   = t;
            const int pl  = e >> 8;
            const int i0  = ((e >> 6) & 3) * 4;
            const int hc0 = (e & 63) * 2;
            const int h   = hc0 >> 4;
            const int prow = (chunk * 2 + pl) * 16;
            const float* ar = &smf[SM_ATT_F + ((pl * 8 + h) * 16 + i0) * 16];
            const float* vb = &smf[SM_V_F + prow * QP + hc0];
            float sx[4] = {}, sy[4] = {};
            #pragma unroll
            for (int j = 0; j < 16; ++j) {
                const float2 vv = *(const float2*)(vb + j * QP);
                #pragma unroll
                for (int i = 0; i < 4; ++i) {
                    const float w = ar[i * 16 + j];
                    sx[i] += w * vv.x;
                    sy[i] += w * vv.y;
                }
            }
            #pragma unroll
            for (int i = 0; i < 4; ++i) {
                const int r = prow + i0 + i;
                const float2 g = *(const float2*)&smf[SM_G_F + r * QP + hc0];
                store_o2(smem, r, hc0, sx[i] * g.x, sy[i] * g.y);
            }
        }
        __syncthreads();   // att buffer reused by next chunk; o stores visible
    }

    // ---------- out GEMM: o @ Wo + bo (Wo staged in B0) ----------
    {
        float c[4][4];
        #pragma unroll
        for (int j = 0; j < 4; ++j)
            #pragma unroll
            for (int q = 0; q < 4; ++q) c[j][q] = 0.0f;

        gemm_dual(base, SM_B0, wm, wn, lane, c);

        const int r  = wm * 16 + (lane >> 2);
        const int r8 = r + 8;
        const long long grow  = (long long)(r  & 15) * PAIRS + pbase + (r  >> 4);
        const long long grow8 = (long long)(r8 & 15) * PAIRS + pbase + (r8 >> 4);
        #pragma unroll
        for (int nb = 0; nb < 4; ++nb) {
            const int col = wn * 32 + nb * 8 + 2 * (lane & 3);
            const float b0 = bo[col], b1 = bo[col + 1];
            *(float2*)&out[grow  * 128 + col] = make_float2(c[nb][0] + b0, c[nb][1] + b1);
            *(float2*)&out[grow8 * 128 + col] = make_float2(c[nb][2] + b0, c[nb][3] + b1);
        }
    }
}

// =====================================================================================
extern "C" void kernel_launch(void* const* d_in, const int* in_sizes, int n_in,
                              void* d_out, int out_size)
{
    (void)in_sizes; (void)n_in; (void)out_size;
    const float* z   = (const float*)d_in[0];
    const float* lnw = (const float*)d_in[1];
    const float* lnb = (const float*)d_in[2];
    const float* Wq  = (const float*)d_in[3];
    const float* Wk  = (const float*)d_in[4];
    const float* Wv  = (const float*)d_in[5];
    const float* Wg  = (const float*)d_in[6];
    const float* bg  = (const float*)d_in[7];
    const float* Wo  = (const float*)d_in[8];
    const float* bo  = (const float*)d_in[9];
    float* out = (float*)d_out;

    cudaFuncSetAttribute(kernel_fused, cudaFuncAttributeMaxDynamicSharedMemorySize, SMEM_TOTAL);

    kernel_prep<<<5, 256>>>(Wq, Wk, Wv, Wg, Wo);
    kernel_fused<<<4096, NT, SMEM_TOTAL>>>(z, lnw, lnb, bg, bo, out);
}

// round 8
// speedup vs baseline: 2.1021x; 1.4513x over previous
#include <cuda_runtime.h>
#include <cuda_fp16.h>
#include <cstdint>

#define PAIRS 16384
#define QP    132            // fp32 g-tile pitch (floats)

// ---------------- smem layout (bytes) ----------------
#define SM_A_HI  0u          // 64x128 fp16 swizzled (zn, later o_hi)
#define SM_A_LO  16384u      // zn_lo, later o_lo
#define SM_B0    32768u      // W image buffer 0 (32KB)
#define SM_B1    65536u      // W image buffer 1 (32KB)
#define SM_QH    98304u      // q fp16 tile (16KB)
#define SM_KH    114688u     // k fp16 tile
#define SM_VH    131072u     // v_hi fp16 tile
#define SM_VL    147456u     // v_lo fp16 tile
#define SM_G_F   40960u      // float index (byte 163840), 64 x QP fp32 g tile
#define SMEM_TOTAL 197632u

#define NT 512               // 16 warps

// ---------------- W images: 5 mats x 128x128 fp16, [n][k] ----------------
__device__ __half g_wimg[5 * 16384];

// ---------------- helpers ----------------
__device__ __forceinline__ uint32_t smem_u32(const void* p) {
    uint32_t a;
    asm("{ .reg .u64 t; cvta.to.shared.u64 t, %1; cvt.u32.u64 %0, t; }" : "=r"(a) : "l"(p));
    return a;
}
__device__ __forceinline__ float sigmoidf_(float x) { return 1.0f / (1.0f + __expf(-x)); }

__device__ __forceinline__ void ldmA4(uint32_t r[4], uint32_t addr) {
    asm volatile("ldmatrix.sync.aligned.m8n8.x4.shared.b16 {%0,%1,%2,%3}, [%4];"
                 : "=r"(r[0]), "=r"(r[1]), "=r"(r[2]), "=r"(r[3]) : "r"(addr));
}
__device__ __forceinline__ void ldmB2(uint32_t r[2], uint32_t addr) {
    asm volatile("ldmatrix.sync.aligned.m8n8.x2.shared.b16 {%0,%1}, [%2];"
                 : "=r"(r[0]), "=r"(r[1]) : "r"(addr));
}
__device__ __forceinline__ void ldmB2t(uint32_t r[2], uint32_t addr) {
    asm volatile("ldmatrix.sync.aligned.m8n8.x2.trans.shared.b16 {%0,%1}, [%2];"
                 : "=r"(r[0]), "=r"(r[1]) : "r"(addr));
}
__device__ __forceinline__ void mma_f16(float c[4], const uint32_t a[4], const uint32_t b[2]) {
    asm volatile(
        "mma.sync.aligned.m16n8k16.row.col.f32.f16.f16.f32 "
        "{%0,%1,%2,%3}, {%4,%5,%6,%7}, {%8,%9}, {%0,%1,%2,%3};"
        : "+f"(c[0]), "+f"(c[1]), "+f"(c[2]), "+f"(c[3])
        : "r"(a[0]), "r"(a[1]), "r"(a[2]), "r"(a[3]), "r"(b[0]), "r"(b[1]));
}
__device__ __forceinline__ void cp_async16(uint32_t dst, const void* src) {
    asm volatile("cp.async.ca.shared.global [%0], [%1], 16;" :: "r"(dst), "l"(src));
}
__device__ __forceinline__ void cp_commit() { asm volatile("cp.async.commit_group;"); }
#define CP_WAIT(n) asm volatile("cp.async.wait_group %0;" :: "n"(n))

__device__ __forceinline__ uint32_t h2bits(float x, float y) {
    __half2 h = __floats2half2_rn(x, y);
    return *(uint32_t*)&h;
}
__device__ __forceinline__ uint32_t h2res(float x, float y, uint32_t hb) {
    __half2 h = *(__half2*)&hb;
    float2 f = __half22float2(h);
    __half2 l = __floats2half2_rn(x - f.x, y - f.y);
    return *(uint32_t*)&l;
}

// =====================================================================================
// prep: round W to fp16, transpose to [n][k]
// =====================================================================================
__global__ void kernel_prep(const float* __restrict__ Wq, const float* __restrict__ Wk,
                            const float* __restrict__ Wv, const float* __restrict__ Wg,
                            const float* __restrict__ Wo)
{
    const int m = blockIdx.x;
    const float* W = (m == 0) ? Wq : (m == 1) ? Wk : (m == 2) ? Wv : (m == 3) ? Wg : Wo;
    __half* hi = g_wimg + (long long)m * 16384;
    for (int idx = threadIdx.x; idx < 16384; idx += blockDim.x) {
        const int n = idx >> 7, k = idx & 127;
        hi[n * 128 + k] = __float2half_rn(W[k * 128 + n]);
    }
}

// ---------------- building blocks ----------------
__device__ __forceinline__ void stage_img(uint32_t base, uint32_t dstOff,
                                          const __half* img, int t)
{
    #pragma unroll
    for (int it = 0; it < 4; ++it) {
        const int idx = t + it * NT;
        const uint32_t row = (uint32_t)(idx >> 4), c = (uint32_t)(idx & 15);
        cp_async16(base + dstOff + row * 256u + ((c ^ (row & 7u)) << 4),
                   img + row * 128u + c * 8u);
    }
}

// single pass: C += Ah*B;  dual: C += (Ah+Al)*B
__device__ __forceinline__ void gemm_pass(uint32_t base, uint32_t bOff, int wm, int wn,
                                          int lane, bool dual, float c[4][4])
{
    const uint32_t arow = (uint32_t)(wm * 16 + (lane & 15));
    const uint32_t asel = (uint32_t)(lane >> 4);
    const int brow0 = wn * 32 + (lane & 7);
    const uint32_t bsel = (uint32_t)((lane >> 3) & 1);
    #pragma unroll
    for (int k = 0; k < 8; ++k) {
        uint32_t ah[4], al[4], b[4][2];
        const uint32_t c16 = (uint32_t)(k * 2) + asel;
        const uint32_t ad = base + arow * 256u + ((c16 ^ (arow & 7u)) << 4);
        ldmA4(ah, ad + SM_A_HI);
        if (dual) ldmA4(al, ad + SM_A_LO);
        #pragma unroll
        for (int nb = 0; nb < 4; ++nb) {
            const uint32_t row = (uint32_t)(brow0 + nb * 8);
            const uint32_t bc = (uint32_t)(k * 2) + bsel;
            ldmB2(b[nb], base + bOff + row * 256u + ((bc ^ (row & 7u)) << 4));
        }
        #pragma unroll
        for (int nb = 0; nb < 4; ++nb) {
            mma_f16(c[nb], ah, b[nb]);
            if (dual) mma_f16(c[nb], al, b[nb]);
        }
    }
}

// LN: split 4 floats -> hi/lo fp16 into swizzled A tiles
__device__ __forceinline__ void store_a4(char* smem, int r, int lane, float4 v)
{
    const uint32_t chunk = (uint32_t)(lane >> 1);
    const uint32_t addr = (uint32_t)r * 256u + ((chunk ^ (uint32_t)(r & 7)) << 4)
                        + (uint32_t)((lane & 1) * 8);
    const __half hx = __float2half_rn(v.x), hy = __float2half_rn(v.y);
    const __half hz = __float2half_rn(v.z), hw = __float2half_rn(v.w);
    const __half2 h01 = __halves2half2(hx, hy), h23 = __halves2half2(hz, hw);
    const __half2 l01 = __halves2half2(__float2half_rn(v.x - __half2float(hx)),
                                       __float2half_rn(v.y - __half2float(hy)));
    const __half2 l23 = __halves2half2(__float2half_rn(v.z - __half2float(hz)),
                                       __float2half_rn(v.w - __half2float(hw)));
    *(__half2*)(smem + SM_A_HI + addr)     = h01;
    *(__half2*)(smem + SM_A_HI + addr + 4) = h23;
    *(__half2*)(smem + SM_A_LO + addr)     = l01;
    *(__half2*)(smem + SM_A_LO + addr + 4) = l23;
}

// store a half2 pair at (row, col..col+1) of a swizzled fp16 tile
__device__ __forceinline__ void store_h2(char* smem, uint32_t tile, int row, int col,
                                         float x, float y)
{
    const uint32_t chunk = (uint32_t)(col >> 3);
    const uint32_t off = (uint32_t)row * 256u + ((chunk ^ (uint32_t)(row & 7)) << 4)
                       + (uint32_t)((col & 7) * 2);
    *(__half2*)(smem + tile + off) = __floats2half2_rn(x, y);
}

// hi/lo split store into two swizzled tiles
__device__ __forceinline__ void store_h2_split(char* smem, uint32_t tHi, uint32_t tLo,
                                               int row, int col, float x, float y)
{
    const uint32_t chunk = (uint32_t)(col >> 3);
    const uint32_t off = (uint32_t)row * 256u + ((chunk ^ (uint32_t)(row & 7)) << 4)
                       + (uint32_t)((col & 7) * 2);
    const __half2 h = __floats2half2_rn(x, y);
    const float2 f = __half22float2(h);
    const __half2 l = __floats2half2_rn(x - f.x, y - f.y);
    *(__half2*)(smem + tHi + off) = h;
    *(__half2*)(smem + tLo + off) = l;
}

__device__ __forceinline__ const __half* wimg(int mat) {
    return g_wimg + (long long)mat * 16384;
}

// =====================================================================================
// fused: LN -> q/k/v/g GEMMs -> HMMA attention (register-resident P) -> out GEMM
// =====================================================================================
__global__ __launch_bounds__(NT, 1)
void kernel_fused(const float* __restrict__ z,
                  const float* __restrict__ lnw, const float* __restrict__ lnb,
                  const float* __restrict__ bg,  const float* __restrict__ bo,
                  float* __restrict__ out)
{
    extern __shared__ char smem[];
    float* smf = (float*)smem;
    const uint32_t base = smem_u32(smem);

    const int t = threadIdx.x, lane = t & 31, warp = t >> 5;
    const int wm = warp >> 2, wn = warp & 3;       // 4x4 warp grid, 16x32 tiles
    const int pbase = blockIdx.x * 4;

    // ---------- LayerNorm -> zn hi/lo ----------
    const float4 lw = *(const float4*)&lnw[lane * 4];
    const float4 lb = *(const float4*)&lnb[lane * 4];
    for (int r = warp; r < 64; r += 16) {
        const long long grow = (long long)(r & 15) * PAIRS + pbase + (r >> 4);
        const float4 zv = *(const float4*)&z[grow * 128 + lane * 4];
        float s  = zv.x + zv.y + zv.z + zv.w;
        float s2 = zv.x*zv.x + zv.y*zv.y + zv.z*zv.z + zv.w*zv.w;
        #pragma unroll
        for (int off = 16; off > 0; off >>= 1) {
            s  += __shfl_xor_sync(0xffffffffu, s,  off);
            s2 += __shfl_xor_sync(0xffffffffu, s2, off);
        }
        const float mu   = s * (1.0f / 128.0f);
        const float var  = s2 * (1.0f / 128.0f) - mu * mu;
        const float rstd = rsqrtf(var + 1e-5f);
        float4 o;
        o.x = (zv.x - mu) * rstd * lw.x + lb.x;
        o.y = (zv.y - mu) * rstd * lw.y + lb.y;
        o.z = (zv.z - mu) * rstd * lw.z + lb.z;
        o.w = (zv.w - mu) * rstd * lw.w + lb.w;
        store_a4(smem, r, lane, o);
    }
    stage_img(base, SM_B0, wimg(0), t);   // Wq
    cp_commit();
    CP_WAIT(0);
    __syncthreads();

    // ---------- projections: q(single), k(single), v(dual), g(single) ----------
    #pragma unroll
    for (int s = 0; s < 4; ++s) {
        const uint32_t buf   = (s & 1) ? SM_B1 : SM_B0;
        const uint32_t other = (s & 1) ? SM_B0 : SM_B1;
        stage_img(base, other, wimg(s + 1), t);   // Wk, Wv, Wg, Wo
        cp_commit();

        float c[4][4];
        #pragma unroll
        for (int j = 0; j < 4; ++j)
            #pragma unroll
            for (int q = 0; q < 4; ++q) c[j][q] = 0.0f;

        gemm_pass(base, buf, wm, wn, lane, (s == 2), c);

        const int r = wm * 16 + (lane >> 2);
        #pragma unroll
        for (int nb = 0; nb < 4; ++nb) {
            const int col = wn * 32 + nb * 8 + 2 * (lane & 3);
            if (s == 0) {
                store_h2(smem, SM_QH, r,     col, c[nb][0], c[nb][1]);
                store_h2(smem, SM_QH, r + 8, col, c[nb][2], c[nb][3]);
            } else if (s == 1) {
                store_h2(smem, SM_KH, r,     col, c[nb][0], c[nb][1]);
                store_h2(smem, SM_KH, r + 8, col, c[nb][2], c[nb][3]);
            } else if (s == 2) {
                store_h2_split(smem, SM_VH, SM_VL, r,     col, c[nb][0], c[nb][1]);
                store_h2_split(smem, SM_VH, SM_VL, r + 8, col, c[nb][2], c[nb][3]);
            } else {
                const float b0 = bg[col], b1 = bg[col + 1];
                *(float2*)&smf[SM_G_F + r * QP + col] =
                    make_float2(sigmoidf_(c[nb][0] + b0), sigmoidf_(c[nb][1] + b1));
                *(float2*)&smf[SM_G_F + (r + 8) * QP + col] =
                    make_float2(sigmoidf_(c[nb][2] + b0), sigmoidf_(c[nb][3] + b1));
            }
        }
        CP_WAIT(0);
        __syncthreads();
    }

    // ---------- attention: fully HMMA, P in registers ----------
    {
        const int pl = warp >> 2;           // pair 0..3
        const int hp = warp & 3;            // head pair -> heads 2hp, 2hp+1
        const int gq = lane >> 2;           // accumulator row group
        const int t2 = (lane & 3) * 2;

        #pragma unroll
        for (int hh = 0; hh < 2; ++hh) {
            const int h = hp * 2 + hh;
            // --- S = 0.25 * q k^T (16x16) ---
            uint32_t aq[4];
            {
                const uint32_t row = (uint32_t)(pl * 16 + (lane & 15));
                const uint32_t cb  = (uint32_t)(h * 2 + (lane >> 4));
                ldmA4(aq, base + SM_QH + row * 256u + ((cb ^ (row & 7u)) << 4));
            }
            float s0[4], s1[4];
            #pragma unroll
            for (int q = 0; q < 4; ++q) { s0[q] = 0.f; s1[q] = 0.f; }
            {
                const uint32_t cb = (uint32_t)(h * 2 + ((lane >> 3) & 1));
                uint32_t bk[2];
                uint32_t row = (uint32_t)(pl * 16 + (lane & 7));
                ldmB2(bk, base + SM_KH + row * 256u + ((cb ^ (row & 7u)) << 4));
                mma_f16(s0, aq, bk);
                row += 8;
                ldmB2(bk, base + SM_KH + row * 256u + ((cb ^ (row & 7u)) << 4));
                mma_f16(s1, aq, bk);
            }
            #pragma unroll
            for (int q = 0; q < 4; ++q) { s0[q] *= 0.25f; s1[q] *= 0.25f; }

            // --- softmax over j (rows gq and gq+8 handled separately) ---
            float mlo = fmaxf(fmaxf(s0[0], s0[1]), fmaxf(s1[0], s1[1]));
            float mhi = fmaxf(fmaxf(s0[2], s0[3]), fmaxf(s1[2], s1[3]));
            mlo = fmaxf(mlo, __shfl_xor_sync(0xffffffffu, mlo, 1));
            mlo = fmaxf(mlo, __shfl_xor_sync(0xffffffffu, mlo, 2));
            mhi = fmaxf(mhi, __shfl_xor_sync(0xffffffffu, mhi, 1));
            mhi = fmaxf(mhi, __shfl_xor_sync(0xffffffffu, mhi, 2));
            s0[0] = __expf(s0[0] - mlo); s0[1] = __expf(s0[1] - mlo);
            s1[0] = __expf(s1[0] - mlo); s1[1] = __expf(s1[1] - mlo);
            s0[2] = __expf(s0[2] - mhi); s0[3] = __expf(s0[3] - mhi);
            s1[2] = __expf(s1[2] - mhi); s1[3] = __expf(s1[3] - mhi);
            float slo = s0[0] + s0[1] + s1[0] + s1[1];
            float shi = s0[2] + s0[3] + s1[2] + s1[3];
            slo += __shfl_xor_sync(0xffffffffu, slo, 1);
            slo += __shfl_xor_sync(0xffffffffu, slo, 2);
            shi += __shfl_xor_sync(0xffffffffu, shi, 1);
            shi += __shfl_xor_sync(0xffffffffu, shi, 2);
            const float ilo = 1.0f / slo, ihi = 1.0f / shi;
            s0[0] *= ilo; s0[1] *= ilo; s1[0] *= ilo; s1[1] *= ilo;
            s0[2] *= ihi; s0[3] *= ihi; s1[2] *= ihi; s1[3] *= ihi;

            // --- P fragments (accumulator layout == A-operand layout) ---
            uint32_t ph[4], plo_[4];
            ph[0] = h2bits(s0[0], s0[1]);  plo_[0] = h2res(s0[0], s0[1], ph[0]);
            ph[1] = h2bits(s0[2], s0[3]);  plo_[1] = h2res(s0[2], s0[3], ph[1]);
            ph[2] = h2bits(s1[0], s1[1]);  plo_[2] = h2res(s1[0], s1[1], ph[2]);
            ph[3] = h2bits(s1[2], s1[3]);  plo_[3] = h2res(s1[2], s1[3], ph[3]);

            // --- O = P V : 3 terms (PhVh + PlVh + PhVl), two col-blocks ---
            float oc[2][4];
            #pragma unroll
            for (int cb = 0; cb < 2; ++cb) {
                #pragma unroll
                for (int q = 0; q < 4; ++q) oc[cb][q] = 0.f;
                const uint32_t row = (uint32_t)(pl * 16 + (lane & 15));
                const uint32_t cbk = (uint32_t)(h * 2 + cb);
                const uint32_t off = row * 256u + ((cbk ^ (row & 7u)) << 4);
                uint32_t bv[2];
                ldmB2t(bv, base + SM_VH + off);
                mma_f16(oc[cb], ph,   bv);
                mma_f16(oc[cb], plo_, bv);
                ldmB2t(bv, base + SM_VL + off);
                mma_f16(oc[cb], ph, bv);
            }

            // --- gate + store o (fp16 hi/lo) into A tiles ---
            const int rlo = pl * 16 + gq, rhi = rlo + 8;
            #pragma unroll
            for (int cb = 0; cb < 2; ++cb) {
                const int col = h * 16 + cb * 8 + t2;
                const float2 glo = *(const float2*)&smf[SM_G_F + rlo * QP + col];
                const float2 ghi = *(const float2*)&smf[SM_G_F + rhi * QP + col];
                store_h2_split(smem, SM_A_HI, SM_A_LO, rlo, col,
                               oc[cb][0] * glo.x, oc[cb][1] * glo.y);
                store_h2_split(smem, SM_A_HI, SM_A_LO, rhi, col,
                               oc[cb][2] * ghi.x, oc[cb][3] * ghi.y);
            }
        }
    }
    __syncthreads();

    // ---------- out GEMM: o @ Wo + bo (Wo staged in B0 at s==3) ----------
    {
        float c[4][4];
        #pragma unroll
        for (int j = 0; j < 4; ++j)
            #pragma unroll
            for (int q = 0; q < 4; ++q) c[j][q] = 0.0f;

        gemm_pass(base, SM_B0, wm, wn, lane, true, c);

        const int r  = wm * 16 + (lane >> 2);
        const int r8 = r + 8;
        const long long grow  = (long long)(r  & 15) * PAIRS + pbase + (r  >> 4);
        const long long grow8 = (long long)(r8 & 15) * PAIRS + pbase + (r8 >> 4);
        #pragma unroll
        for (int nb = 0; nb < 4; ++nb) {
            const int col = wn * 32 + nb * 8 + 2 * (lane & 3);
            const float b0 = bo[col], b1 = bo[col + 1];
            *(float2*)&out[grow  * 128 + col] = make_float2(c[nb][0] + b0, c[nb][1] + b1);
            *(float2*)&out[grow8 * 128 + col] = make_float2(c[nb][2] + b0, c[nb][3] + b1);
        }
    }
}

// =====================================================================================
extern "C" void kernel_launch(void* const* d_in, const int* in_sizes, int n_in,
                              void* d_out, int out_size)
{
    (void)in_sizes; (void)n_in; (void)out_size;
    const float* z   = (const float*)d_in[0];
    const float* lnw = (const float*)d_in[1];
    const float* lnb = (const float*)d_in[2];
    const float* Wq  = (const float*)d_in[3];
    const float* Wk  = (const float*)d_in[4];
    const float* Wv  = (const float*)d_in[5];
    const float* Wg  = (const float*)d_in[6];
    const float* bg  = (const float*)d_in[7];
    const float* Wo  = (const float*)d_in[8];
    const float* bo  = (const float*)d_in[9];
    float* out = (float*)d_out;

    cudaFuncSetAttribute(kernel_fused, cudaFuncAttributeMaxDynamicSharedMemorySize, SMEM_TOTAL);

    kernel_prep<<<5, 256>>>(Wq, Wk, Wv, Wg, Wo);
    kernel_fused<<<4096, NT, SMEM_TOTAL>>>(z, lnw, lnb, bg, bo, out);
}

// round 9
// speedup vs baseline: 2.2810x; 1.0852x over previous
#include <cuda_runtime.h>
#include <cuda_fp16.h>
#include <cstdint>

#define PAIRS 16384

// ---------------- smem layout (bytes) ----------------
#define SM_A_HI  0u          // 32x128 fp16 swizzled (zn, later o_hi)
#define SM_A_LO  8192u       // zn_lo / o_lo
#define SM_B0    16384u      // W image buffer 0 (32KB)
#define SM_B1    49152u      // W image buffer 1 (32KB)
#define SMEM_TOTAL 81920u

#define NT 256               // 8 warps, 2 CTAs/SM

// ---------------- W images: 5 mats x 128x128 fp16, [n][k] ----------------
__device__ __half g_wimg[5 * 16384];

// ---------------- helpers ----------------
__device__ __forceinline__ uint32_t smem_u32(const void* p) {
    uint32_t a;
    asm("{ .reg .u64 t; cvta.to.shared.u64 t, %1; cvt.u32.u64 %0, t; }" : "=r"(a) : "l"(p));
    return a;
}
__device__ __forceinline__ float sigmoidf_(float x) { return 1.0f / (1.0f + __expf(-x)); }

__device__ __forceinline__ void ldmA4(uint32_t r[4], uint32_t addr) {
    asm volatile("ldmatrix.sync.aligned.m8n8.x4.shared.b16 {%0,%1,%2,%3}, [%4];"
                 : "=r"(r[0]), "=r"(r[1]), "=r"(r[2]), "=r"(r[3]) : "r"(addr));
}
__device__ __forceinline__ void ldmB2(uint32_t r[2], uint32_t addr) {
    asm volatile("ldmatrix.sync.aligned.m8n8.x2.shared.b16 {%0,%1}, [%2];"
                 : "=r"(r[0]), "=r"(r[1]) : "r"(addr));
}
__device__ __forceinline__ void mma_f16(float c[4], const uint32_t a[4], const uint32_t b[2]) {
    asm volatile(
        "mma.sync.aligned.m16n8k16.row.col.f32.f16.f16.f32 "
        "{%0,%1,%2,%3}, {%4,%5,%6,%7}, {%8,%9}, {%0,%1,%2,%3};"
        : "+f"(c[0]), "+f"(c[1]), "+f"(c[2]), "+f"(c[3])
        : "r"(a[0]), "r"(a[1]), "r"(a[2]), "r"(a[3]), "r"(b[0]), "r"(b[1]));
}
__device__ __forceinline__ uint32_t movm(uint32_t a) {
    uint32_t d;
    asm volatile("movmatrix.sync.aligned.m8n8.trans.b16 %0, %1;" : "=r"(d) : "r"(a));
    return d;
}
__device__ __forceinline__ void cp_async16(uint32_t dst, const void* src) {
    asm volatile("cp.async.ca.shared.global [%0], [%1], 16;" :: "r"(dst), "l"(src));
}
__device__ __forceinline__ void cp_commit() { asm volatile("cp.async.commit_group;"); }
#define CP_WAIT(n) asm volatile("cp.async.wait_group %0;" :: "n"(n))

__device__ __forceinline__ uint32_t h2bits(float x, float y) {
    __half2 h = __floats2half2_rn(x, y);
    return *(uint32_t*)&h;
}
__device__ __forceinline__ uint32_t h2res(float x, float y, uint32_t hb) {
    __half2 h = *(__half2*)&hb;
    float2 f = __half22float2(h);
    __half2 l = __floats2half2_rn(x - f.x, y - f.y);
    return *(uint32_t*)&l;
}

// =====================================================================================
// prep: round W to fp16, transpose to [n][k]
// =====================================================================================
__global__ void kernel_prep(const float* __restrict__ Wq, const float* __restrict__ Wk,
                            const float* __restrict__ Wv, const float* __restrict__ Wg,
                            const float* __restrict__ Wo)
{
    const int m = blockIdx.x;
    const float* W = (m == 0) ? Wq : (m == 1) ? Wk : (m == 2) ? Wv : (m == 3) ? Wg : Wo;
    __half* hi = g_wimg + (long long)m * 16384;
    for (int idx = threadIdx.x; idx < 16384; idx += blockDim.x) {
        const int n = idx >> 7, k = idx & 127;
        hi[n * 128 + k] = __float2half_rn(W[k * 128 + n]);
    }
}

// ---------------- building blocks ----------------
__device__ __forceinline__ void stage_img(uint32_t base, uint32_t dstOff,
                                          const __half* img, int t)
{
    #pragma unroll
    for (int it = 0; it < 8; ++it) {
        const int idx = t + it * NT;
        const uint32_t row = (uint32_t)(idx >> 4), c = (uint32_t)(idx & 15);
        cp_async16(base + dstOff + row * 256u + ((c ^ (row & 7u)) << 4),
                   img + row * 128u + c * 8u);
    }
}

// single pass: C += Ah*B;  dual: C += (Ah+Al)*B.  Warp tile 16x32 (wm 0..1, wn 0..3).
__device__ __forceinline__ void gemm_pass(uint32_t base, uint32_t bOff, int wm, int wn,
                                          int lane, bool dual, float c[4][4])
{
    const uint32_t arow = (uint32_t)(wm * 16 + (lane & 15));
    const uint32_t asel = (uint32_t)(lane >> 4);
    const int brow0 = wn * 32 + (lane & 7);
    const uint32_t bsel = (uint32_t)((lane >> 3) & 1);
    #pragma unroll
    for (int k = 0; k < 8; ++k) {
        uint32_t ah[4], al[4], b[4][2];
        const uint32_t c16 = (uint32_t)(k * 2) + asel;
        const uint32_t ad = base + arow * 256u + ((c16 ^ (arow & 7u)) << 4);
        ldmA4(ah, ad + SM_A_HI);
        if (dual) ldmA4(al, ad + SM_A_LO);
        #pragma unroll
        for (int nb = 0; nb < 4; ++nb) {
            const uint32_t row = (uint32_t)(brow0 + nb * 8);
            const uint32_t bc = (uint32_t)(k * 2) + bsel;
            ldmB2(b[nb], base + bOff + row * 256u + ((bc ^ (row & 7u)) << 4));
        }
        #pragma unroll
        for (int nb = 0; nb < 4; ++nb) {
            mma_f16(c[nb], ah, b[nb]);
            if (dual) mma_f16(c[nb], al, b[nb]);
        }
    }
}

// LN: split 4 floats -> hi/lo fp16 into swizzled A tiles
__device__ __forceinline__ void store_a4(char* smem, int r, int lane, float4 v)
{
    const uint32_t chunk = (uint32_t)(lane >> 1);
    const uint32_t addr = (uint32_t)r * 256u + ((chunk ^ (uint32_t)(r & 7)) << 4)
                        + (uint32_t)((lane & 1) * 8);
    const __half hx = __float2half_rn(v.x), hy = __float2half_rn(v.y);
    const __half hz = __float2half_rn(v.z), hw = __float2half_rn(v.w);
    const __half2 h01 = __halves2half2(hx, hy), h23 = __halves2half2(hz, hw);
    const __half2 l01 = __halves2half2(__float2half_rn(v.x - __half2float(hx)),
                                       __float2half_rn(v.y - __half2float(hy)));
    const __half2 l23 = __halves2half2(__float2half_rn(v.z - __half2float(hz)),
                                       __float2half_rn(v.w - __half2float(hw)));
    *(__half2*)(smem + SM_A_HI + addr)     = h01;
    *(__half2*)(smem + SM_A_HI + addr + 4) = h23;
    *(__half2*)(smem + SM_A_LO + addr)     = l01;
    *(__half2*)(smem + SM_A_LO + addr + 4) = l23;
}

// hi/lo split store of one half2 into the A tiles
__device__ __forceinline__ void store_o2(char* smem, int row, int col, float x, float y)
{
    const uint32_t chunk = (uint32_t)(col >> 3);
    const uint32_t off = (uint32_t)row * 256u + ((chunk ^ (uint32_t)(row & 7)) << 4)
                       + (uint32_t)((col & 7) * 2);
    const __half2 h = __floats2half2_rn(x, y);
    const float2 f = __half22float2(h);
    const __half2 l = __floats2half2_rn(x - f.x, y - f.y);
    *(__half2*)(smem + SM_A_HI + off) = h;
    *(__half2*)(smem + SM_A_LO + off) = l;
}

__device__ __forceinline__ const __half* wimg(int mat) {
    return g_wimg + (long long)mat * 16384;
}

// =====================================================================================
// fused, register-resident: LN -> q/k/v/g in-register -> HMMA attention -> out GEMM
// 2 pairs per CTA, 8 warps; warp (wm=pair, wn=head-pair)
// =====================================================================================
__global__ __launch_bounds__(NT, 2)
void kernel_fused(const float* __restrict__ z,
                  const float* __restrict__ lnw, const float* __restrict__ lnb,
                  const float* __restrict__ bg,  const float* __restrict__ bo,
                  float* __restrict__ out)
{
    extern __shared__ char smem[];
    const uint32_t base = smem_u32(smem);

    const int t = threadIdx.x, lane = t & 31, warp = t >> 5;
    const int wm = warp >> 2, wn = warp & 3;
    const int pbase = blockIdx.x * 2;

    // ---------- stage Wq; LayerNorm -> zn hi/lo ----------
    stage_img(base, SM_B0, wimg(0), t);
    cp_commit();
    {
        const float4 lw = *(const float4*)&lnw[lane * 4];
        const float4 lb = *(const float4*)&lnb[lane * 4];
        for (int r = warp; r < 32; r += 8) {
            const long long grow = (long long)(r & 15) * PAIRS + pbase + (r >> 4);
            const float4 zv = *(const float4*)&z[grow * 128 + lane * 4];
            float s  = zv.x + zv.y + zv.z + zv.w;
            float s2 = zv.x*zv.x + zv.y*zv.y + zv.z*zv.z + zv.w*zv.w;
            #pragma unroll
            for (int off = 16; off > 0; off >>= 1) {
                s  += __shfl_xor_sync(0xffffffffu, s,  off);
                s2 += __shfl_xor_sync(0xffffffffu, s2, off);
            }
            const float mu   = s * (1.0f / 128.0f);
            const float var  = s2 * (1.0f / 128.0f) - mu * mu;
            const float rstd = rsqrtf(var + 1e-5f);
            float4 o;
            o.x = (zv.x - mu) * rstd * lw.x + lb.x;
            o.y = (zv.y - mu) * rstd * lw.y + lb.y;
            o.z = (zv.z - mu) * rstd * lw.z + lb.z;
            o.w = (zv.w - mu) * rstd * lw.w + lb.w;
            store_a4(smem, r, lane, o);
        }
    }
    CP_WAIT(0);
    __syncthreads();                 // zn + Wq ready

    // ---------- q projection (single) -> A fragments ----------
    uint32_t qf[2][4];
    stage_img(base, SM_B1, wimg(1), t);   // Wk
    cp_commit();
    {
        float c[4][4];
        #pragma unroll
        for (int j = 0; j < 4; ++j) { c[j][0]=0.f; c[j][1]=0.f; c[j][2]=0.f; c[j][3]=0.f; }
        gemm_pass(base, SM_B0, wm, wn, lane, false, c);
        #pragma unroll
        for (int hh = 0; hh < 2; ++hh) {
            qf[hh][0] = h2bits(c[2*hh][0],   c[2*hh][1]);
            qf[hh][1] = h2bits(c[2*hh][2],   c[2*hh][3]);
            qf[hh][2] = h2bits(c[2*hh+1][0], c[2*hh+1][1]);
            qf[hh][3] = h2bits(c[2*hh+1][2], c[2*hh+1][3]);
        }
    }
    CP_WAIT(0);
    __syncthreads();                 // Wk ready; B0 reads done

    // ---------- k projection (single) -> B fragments; S + softmax + P ----------
    uint32_t pf[2][4], plf[2][4];
    stage_img(base, SM_B0, wimg(2), t);   // Wv
    cp_commit();
    {
        float c[4][4];
        #pragma unroll
        for (int j = 0; j < 4; ++j) { c[j][0]=0.f; c[j][1]=0.f; c[j][2]=0.f; c[j][3]=0.f; }
        gemm_pass(base, SM_B1, wm, wn, lane, false, c);
        #pragma unroll
        for (int hh = 0; hh < 2; ++hh) {
            uint32_t kf[4];
            kf[0] = h2bits(c[2*hh][0],   c[2*hh][1]);    // j0-7,  c0-7
            kf[1] = h2bits(c[2*hh+1][0], c[2*hh+1][1]);  // j0-7,  c8-15
            kf[2] = h2bits(c[2*hh][2],   c[2*hh][3]);    // j8-15, c0-7
            kf[3] = h2bits(c[2*hh+1][2], c[2*hh+1][3]);  // j8-15, c8-15

            float s0[4] = {0.f,0.f,0.f,0.f}, s1[4] = {0.f,0.f,0.f,0.f};
            mma_f16(s0, qf[hh], &kf[0]);     // j 0-7
            mma_f16(s1, qf[hh], &kf[2]);     // j 8-15
            #pragma unroll
            for (int q = 0; q < 4; ++q) { s0[q] *= 0.25f; s1[q] *= 0.25f; }

            float mlo = fmaxf(fmaxf(s0[0], s0[1]), fmaxf(s1[0], s1[1]));
            float mhi = fmaxf(fmaxf(s0[2], s0[3]), fmaxf(s1[2], s1[3]));
            mlo = fmaxf(mlo, __shfl_xor_sync(0xffffffffu, mlo, 1));
            mlo = fmaxf(mlo, __shfl_xor_sync(0xffffffffu, mlo, 2));
            mhi = fmaxf(mhi, __shfl_xor_sync(0xffffffffu, mhi, 1));
            mhi = fmaxf(mhi, __shfl_xor_sync(0xffffffffu, mhi, 2));
            s0[0] = __expf(s0[0] - mlo); s0[1] = __expf(s0[1] - mlo);
            s1[0] = __expf(s1[0] - mlo); s1[1] = __expf(s1[1] - mlo);
            s0[2] = __expf(s0[2] - mhi); s0[3] = __expf(s0[3] - mhi);
            s1[2] = __expf(s1[2] - mhi); s1[3] = __expf(s1[3] - mhi);
            float slo = s0[0] + s0[1] + s1[0] + s1[1];
            float shi = s0[2] + s0[3] + s1[2] + s1[3];
            slo += __shfl_xor_sync(0xffffffffu, slo, 1);
            slo += __shfl_xor_sync(0xffffffffu, slo, 2);
            shi += __shfl_xor_sync(0xffffffffu, shi, 1);
            shi += __shfl_xor_sync(0xffffffffu, shi, 2);
            const float ilo = 1.0f / slo, ihi = 1.0f / shi;
            s0[0] *= ilo; s0[1] *= ilo; s1[0] *= ilo; s1[1] *= ilo;
            s0[2] *= ihi; s0[3] *= ihi; s1[2] *= ihi; s1[3] *= ihi;

            pf[hh][0] = h2bits(s0[0], s0[1]);  plf[hh][0] = h2res(s0[0], s0[1], pf[hh][0]);
            pf[hh][1] = h2bits(s0[2], s0[3]);  plf[hh][1] = h2res(s0[2], s0[3], pf[hh][1]);
            pf[hh][2] = h2bits(s1[0], s1[1]);  plf[hh][2] = h2res(s1[0], s1[1], pf[hh][2]);
            pf[hh][3] = h2bits(s1[2], s1[3]);  plf[hh][3] = h2res(s1[2], s1[3], pf[hh][3]);
        }
    }
    CP_WAIT(0);
    __syncthreads();                 // Wv ready; B1 reads done

    // ---------- v projection (dual) -> in-register transpose -> O = P V ----------
    float oc[2][2][4];
    stage_img(base, SM_B1, wimg(3), t);   // Wg
    cp_commit();
    {
        float c[4][4];
        #pragma unroll
        for (int j = 0; j < 4; ++j) { c[j][0]=0.f; c[j][1]=0.f; c[j][2]=0.f; c[j][3]=0.f; }
        gemm_pass(base, SM_B0, wm, wn, lane, true, c);
        #pragma unroll
        for (int hh = 0; hh < 2; ++hh) {
            #pragma unroll
            for (int cb = 0; cb < 2; ++cb) {
                const int nb = hh * 2 + cb;
                const uint32_t m0 = h2bits(c[nb][0], c[nb][1]);
                const uint32_t m1 = h2bits(c[nb][2], c[nb][3]);
                const uint32_t r0 = h2res(c[nb][0], c[nb][1], m0);
                const uint32_t r1 = h2res(c[nb][2], c[nb][3], m1);
                uint32_t bh[2], bl[2];
                bh[0] = movm(m0); bh[1] = movm(m1);
                bl[0] = movm(r0); bl[1] = movm(r1);
                float* o = oc[hh][cb];
                o[0] = 0.f; o[1] = 0.f; o[2] = 0.f; o[3] = 0.f;
                mma_f16(o, pf[hh],  bh);
                mma_f16(o, plf[hh], bh);
                mma_f16(o, pf[hh],  bl);
            }
        }
    }
    CP_WAIT(0);
    __syncthreads();                 // Wg ready; B0 reads done

    // ---------- g projection (single) -> gate -> store o into A tiles ----------
    stage_img(base, SM_B0, wimg(4), t);   // Wo
    cp_commit();
    {
        float c[4][4];
        #pragma unroll
        for (int j = 0; j < 4; ++j) { c[j][0]=0.f; c[j][1]=0.f; c[j][2]=0.f; c[j][3]=0.f; }
        gemm_pass(base, SM_B1, wm, wn, lane, false, c);
        __syncthreads();             // ALL warps done reading zn before o overwrites A
        #pragma unroll
        for (int hh = 0; hh < 2; ++hh) {
            #pragma unroll
            for (int cb = 0; cb < 2; ++cb) {
                const int nb = hh * 2 + cb;
                const int col = wn * 32 + nb * 8 + 2 * (lane & 3);
                const float b0 = bg[col], b1 = bg[col + 1];
                float* o = oc[hh][cb];
                o[0] *= sigmoidf_(c[nb][0] + b0);
                o[1] *= sigmoidf_(c[nb][1] + b1);
                o[2] *= sigmoidf_(c[nb][2] + b0);
                o[3] *= sigmoidf_(c[nb][3] + b1);
                const int r = wm * 16 + (lane >> 2);
                store_o2(smem, r,     col, o[0], o[1]);
                store_o2(smem, r + 8, col, o[2], o[3]);
            }
        }
    }
    CP_WAIT(0);
    __syncthreads();                 // o visible; Wo ready

    // ---------- out GEMM: o @ Wo + bo ----------
    {
        float c[4][4];
        #pragma unroll
        for (int j = 0; j < 4; ++j) { c[j][0]=0.f; c[j][1]=0.f; c[j][2]=0.f; c[j][3]=0.f; }
        gemm_pass(base, SM_B0, wm, wn, lane, true, c);

        const int r  = wm * 16 + (lane >> 2);
        const int r8 = r + 8;
        const long long grow  = (long long)(r  & 15) * PAIRS + pbase + (r  >> 4);
        const long long grow8 = (long long)(r8 & 15) * PAIRS + pbase + (r8 >> 4);
        #pragma unroll
        for (int nb = 0; nb < 4; ++nb) {
            const int col = wn * 32 + nb * 8 + 2 * (lane & 3);
            const float b0 = bo[col], b1 = bo[col + 1];
            *(float2*)&out[grow  * 128 + col] = make_float2(c[nb][0] + b0, c[nb][1] + b1);
            *(float2*)&out[grow8 * 128 + col] = make_float2(c[nb][2] + b0, c[nb][3] + b1);
        }
    }
}

// =====================================================================================
extern "C" void kernel_launch(void* const* d_in, const int* in_sizes, int n_in,
                              void* d_out, int out_size)
{
    (void)in_sizes; (void)n_in; (void)out_size;
    const float* z   = (const float*)d_in[0];
    const float* lnw = (const float*)d_in[1];
    const float* lnb = (const float*)d_in[2];
    const float* Wq  = (const float*)d_in[3];
    const float* Wk  = (const float*)d_in[4];
    const float* Wv  = (const float*)d_in[5];
    const float* Wg  = (const float*)d_in[6];
    const float* bg  = (const float*)d_in[7];
    const float* Wo  = (const float*)d_in[8];
    const float* bo  = (const float*)d_in[9];
    float* out = (float*)d_out;

    cudaFuncSetAttribute(kernel_fused, cudaFuncAttributeMaxDynamicSharedMemorySize, SMEM_TOTAL);

    kernel_prep<<<5, 256>>>(Wq, Wk, Wv, Wg, Wo);
    kernel_fused<<<PAIRS / 2, NT, SMEM_TOTAL>>>(z, lnw, lnb, bg, bo, out);
}

// round 10
// speedup vs baseline: 2.4260x; 1.0635x over previous
#include <cuda_runtime.h>
#include <cuda_fp16.h>
#include <cstdint>

#define PAIRS 16384

// ---------------- smem layout (bytes) ----------------
#define SM_A_HI  0u          // 32x128 fp16 swizzled (zn, later o_hi)
#define SM_A_LO  8192u       // zn_lo / o_lo
#define SM_B0    16384u      // W image buffer 0 (32KB)
#define SM_B1    49152u      // W image buffer 1 (32KB)
#define SMEM_TOTAL 81920u

#define NT 256               // 8 warps, 2 CTAs/SM

// ---------------- W images: 5 mats x 128x128 fp16, [n][k] ----------------
__device__ __half g_wimg[5 * 16384];

// ---------------- helpers ----------------
__device__ __forceinline__ uint32_t smem_u32(const void* p) {
    uint32_t a;
    asm("{ .reg .u64 t; cvta.to.shared.u64 t, %1; cvt.u32.u64 %0, t; }" : "=r"(a) : "l"(p));
    return a;
}
__device__ __forceinline__ float sigmoidf_(float x) { return 1.0f / (1.0f + __expf(-x)); }

__device__ __forceinline__ void ldmA4(uint32_t r[4], uint32_t addr) {
    asm volatile("ldmatrix.sync.aligned.m8n8.x4.shared.b16 {%0,%1,%2,%3}, [%4];"
                 : "=r"(r[0]), "=r"(r[1]), "=r"(r[2]), "=r"(r[3]) : "r"(addr));
}
__device__ __forceinline__ void ldmB2(uint32_t r[2], uint32_t addr) {
    asm volatile("ldmatrix.sync.aligned.m8n8.x2.shared.b16 {%0,%1}, [%2];"
                 : "=r"(r[0]), "=r"(r[1]) : "r"(addr));
}
__device__ __forceinline__ void mma_f16(float c[4], const uint32_t a[4], const uint32_t b[2]) {
    asm volatile(
        "mma.sync.aligned.m16n8k16.row.col.f32.f16.f16.f32 "
        "{%0,%1,%2,%3}, {%4,%5,%6,%7}, {%8,%9}, {%0,%1,%2,%3};"
        : "+f"(c[0]), "+f"(c[1]), "+f"(c[2]), "+f"(c[3])
        : "r"(a[0]), "r"(a[1]), "r"(a[2]), "r"(a[3]), "r"(b[0]), "r"(b[1]));
}
__device__ __forceinline__ uint32_t movm(uint32_t a) {
    uint32_t d;
    asm volatile("movmatrix.sync.aligned.m8n8.trans.b16 %0, %1;" : "=r"(d) : "r"(a));
    return d;
}
__device__ __forceinline__ void cp_async16(uint32_t dst, const void* src) {
    asm volatile("cp.async.ca.shared.global [%0], [%1], 16;" :: "r"(dst), "l"(src));
}
__device__ __forceinline__ void cp_commit() { asm volatile("cp.async.commit_group;"); }
#define CP_WAIT(n) asm volatile("cp.async.wait_group %0;" :: "n"(n))

__device__ __forceinline__ uint32_t h2bits(float x, float y) {
    __half2 h = __floats2half2_rn(x, y);
    return *(uint32_t*)&h;
}
__device__ __forceinline__ uint32_t h2res(float x, float y, uint32_t hb) {
    __half2 h = *(__half2*)&hb;
    float2 f = __half22float2(h);
    __half2 l = __floats2half2_rn(x - f.x, y - f.y);
    return *(uint32_t*)&l;
}

// =====================================================================================
// prep: round W to fp16, transpose to [n][k]
// =====================================================================================
__global__ void kernel_prep(const float* __restrict__ Wq, const float* __restrict__ Wk,
                            const float* __restrict__ Wv, const float* __restrict__ Wg,
                            const float* __restrict__ Wo)
{
    const int m = blockIdx.x;
    const float* W = (m == 0) ? Wq : (m == 1) ? Wk : (m == 2) ? Wv : (m == 3) ? Wg : Wo;
    __half* hi = g_wimg + (long long)m * 16384;
    for (int idx = threadIdx.x; idx < 16384; idx += blockDim.x) {
        const int n = idx >> 7, k = idx & 127;
        hi[n * 128 + k] = __float2half_rn(W[k * 128 + n]);
    }
}

// ---------------- building blocks ----------------
__device__ __forceinline__ void stage_img(uint32_t base, uint32_t dstOff,
                                          const __half* img, int t)
{
    #pragma unroll
    for (int it = 0; it < 8; ++it) {
        const int idx = t + it * NT;
        const uint32_t row = (uint32_t)(idx >> 4), c = (uint32_t)(idx & 15);
        cp_async16(base + dstOff + row * 256u + ((c ^ (row & 7u)) << 4),
                   img + row * 128u + c * 8u);
    }
}

// fused single+single: cq += Ah*B0, ck += Ah*B1 (shared A loads)
__device__ __forceinline__ void gemm_qk(uint32_t base, int wm, int wn, int lane,
                                        float cq[4][4], float ck[4][4])
{
    const uint32_t arow = (uint32_t)(wm * 16 + (lane & 15));
    const uint32_t asel = (uint32_t)(lane >> 4);
    const int brow0 = wn * 32 + (lane & 7);
    const uint32_t bsel = (uint32_t)((lane >> 3) & 1);
    #pragma unroll
    for (int k = 0; k < 8; ++k) {
        uint32_t ah[4], b0[4][2], b1[4][2];
        const uint32_t c16 = (uint32_t)(k * 2) + asel;
        ldmA4(ah, base + SM_A_HI + arow * 256u + ((c16 ^ (arow & 7u)) << 4));
        #pragma unroll
        for (int nb = 0; nb < 4; ++nb) {
            const uint32_t row = (uint32_t)(brow0 + nb * 8);
            const uint32_t bc = (uint32_t)(k * 2) + bsel;
            const uint32_t off = row * 256u + ((bc ^ (row & 7u)) << 4);
            ldmB2(b0[nb], base + SM_B0 + off);
            ldmB2(b1[nb], base + SM_B1 + off);
        }
        #pragma unroll
        for (int nb = 0; nb < 4; ++nb) {
            mma_f16(cq[nb], ah, b0[nb]);
            mma_f16(ck[nb], ah, b1[nb]);
        }
    }
}

// fused dual+single: cv += (Ah+Al)*B0, cg += Ah*B1 (shared A loads)
__device__ __forceinline__ void gemm_vg(uint32_t base, int wm, int wn, int lane,
                                        float cv[4][4], float cg[4][4])
{
    const uint32_t arow = (uint32_t)(wm * 16 + (lane & 15));
    const uint32_t asel = (uint32_t)(lane >> 4);
    const int brow0 = wn * 32 + (lane & 7);
    const uint32_t bsel = (uint32_t)((lane >> 3) & 1);
    #pragma unroll
    for (int k = 0; k < 8; ++k) {
        uint32_t ah[4], al[4], b0[4][2], b1[4][2];
        const uint32_t c16 = (uint32_t)(k * 2) + asel;
        const uint32_t ad = base + arow * 256u + ((c16 ^ (arow & 7u)) << 4);
        ldmA4(ah, ad + SM_A_HI);
        ldmA4(al, ad + SM_A_LO);
        #pragma unroll
        for (int nb = 0; nb < 4; ++nb) {
            const uint32_t row = (uint32_t)(brow0 + nb * 8);
            const uint32_t bc = (uint32_t)(k * 2) + bsel;
            const uint32_t off = row * 256u + ((bc ^ (row & 7u)) << 4);
            ldmB2(b0[nb], base + SM_B0 + off);
            ldmB2(b1[nb], base + SM_B1 + off);
        }
        #pragma unroll
        for (int nb = 0; nb < 4; ++nb) {
            mma_f16(cv[nb], ah, b0[nb]);
            mma_f16(cg[nb], ah, b1[nb]);
            mma_f16(cv[nb], al, b0[nb]);
        }
    }
}

// dual pass for out GEMM: c += (Ah+Al)*B
__device__ __forceinline__ void gemm_dual(uint32_t base, uint32_t bOff, int wm, int wn,
                                          int lane, float c[4][4])
{
    const uint32_t arow = (uint32_t)(wm * 16 + (lane & 15));
    const uint32_t asel = (uint32_t)(lane >> 4);
    const int brow0 = wn * 32 + (lane & 7);
    const uint32_t bsel = (uint32_t)((lane >> 3) & 1);
    #pragma unroll
    for (int k = 0; k < 8; ++k) {
        uint32_t ah[4], al[4], b[4][2];
        const uint32_t c16 = (uint32_t)(k * 2) + asel;
        const uint32_t ad = base + arow * 256u + ((c16 ^ (arow & 7u)) << 4);
        ldmA4(ah, ad + SM_A_HI);
        ldmA4(al, ad + SM_A_LO);
        #pragma unroll
        for (int nb = 0; nb < 4; ++nb) {
            const uint32_t row = (uint32_t)(brow0 + nb * 8);
            const uint32_t bc = (uint32_t)(k * 2) + bsel;
            ldmB2(b[nb], base + bOff + row * 256u + ((bc ^ (row & 7u)) << 4));
        }
        #pragma unroll
        for (int nb = 0; nb < 4; ++nb) {
            mma_f16(c[nb], ah, b[nb]);
            mma_f16(c[nb], al, b[nb]);
        }
    }
}

// LN: split 4 floats -> hi/lo fp16 into swizzled A tiles
__device__ __forceinline__ void store_a4(char* smem, int r, int lane, float4 v)
{
    const uint32_t chunk = (uint32_t)(lane >> 1);
    const uint32_t addr = (uint32_t)r * 256u + ((chunk ^ (uint32_t)(r & 7)) << 4)
                        + (uint32_t)((lane & 1) * 8);
    const __half hx = __float2half_rn(v.x), hy = __float2half_rn(v.y);
    const __half hz = __float2half_rn(v.z), hw = __float2half_rn(v.w);
    const __half2 h01 = __halves2half2(hx, hy), h23 = __halves2half2(hz, hw);
    const __half2 l01 = __halves2half2(__float2half_rn(v.x - __half2float(hx)),
                                       __float2half_rn(v.y - __half2float(hy)));
    const __half2 l23 = __halves2half2(__float2half_rn(v.z - __half2float(hz)),
                                       __float2half_rn(v.w - __half2float(hw)));
    *(__half2*)(smem + SM_A_HI + addr)     = h01;
    *(__half2*)(smem + SM_A_HI + addr + 4) = h23;
    *(__half2*)(smem + SM_A_LO + addr)     = l01;
    *(__half2*)(smem + SM_A_LO + addr + 4) = l23;
}

// hi/lo split store of one half2 into the A tiles
__device__ __forceinline__ void store_o2(char* smem, int row, int col, float x, float y)
{
    const uint32_t chunk = (uint32_t)(col >> 3);
    const uint32_t off = (uint32_t)row * 256u + ((chunk ^ (uint32_t)(row & 7)) << 4)
                       + (uint32_t)((col & 7) * 2);
    const __half2 h = __floats2half2_rn(x, y);
    const float2 f = __half22float2(h);
    const __half2 l = __floats2half2_rn(x - f.x, y - f.y);
    *(__half2*)(smem + SM_A_HI + off) = h;
    *(__half2*)(smem + SM_A_LO + off) = l;
}

__device__ __forceinline__ const __half* wimg(int mat) {
    return g_wimg + (long long)mat * 16384;
}

// =====================================================================================
// fused, register-resident, A-shared GEMM pairs:
// LN -> (q|k fused) -> S/softmax/P -> (v|g fused) -> O=PV -> gate -> out GEMM
// 2 pairs per CTA, 8 warps; warp (wm=pair, wn=head-pair)
// =====================================================================================
__global__ __launch_bounds__(NT, 2)
void kernel_fused(const float* __restrict__ z,
                  const float* __restrict__ lnw, const float* __restrict__ lnb,
                  const float* __restrict__ bg,  const float* __restrict__ bo,
                  float* __restrict__ out)
{
    extern __shared__ char smem[];
    const uint32_t base = smem_u32(smem);

    const int t = threadIdx.x, lane = t & 31, warp = t >> 5;
    const int wm = warp >> 2, wn = warp & 3;
    const int pbase = blockIdx.x * 2;

    // ---------- stage Wq+Wk; LayerNorm -> zn hi/lo ----------
    stage_img(base, SM_B0, wimg(0), t);
    stage_img(base, SM_B1, wimg(1), t);
    cp_commit();
    {
        const float4 lw = *(const float4*)&lnw[lane * 4];
        const float4 lb = *(const float4*)&lnb[lane * 4];
        for (int r = warp; r < 32; r += 8) {
            const long long grow = (long long)(r & 15) * PAIRS + pbase + (r >> 4);
            const float4 zv = *(const float4*)&z[grow * 128 + lane * 4];
            float s  = zv.x + zv.y + zv.z + zv.w;
            float s2 = zv.x*zv.x + zv.y*zv.y + zv.z*zv.z + zv.w*zv.w;
            #pragma unroll
            for (int off = 16; off > 0; off >>= 1) {
                s  += __shfl_xor_sync(0xffffffffu, s,  off);
                s2 += __shfl_xor_sync(0xffffffffu, s2, off);
            }
            const float mu   = s * (1.0f / 128.0f);
            const float var  = s2 * (1.0f / 128.0f) - mu * mu;
            const float rstd = rsqrtf(var + 1e-5f);
            float4 o;
            o.x = (zv.x - mu) * rstd * lw.x + lb.x;
            o.y = (zv.y - mu) * rstd * lw.y + lb.y;
            o.z = (zv.z - mu) * rstd * lw.z + lb.z;
            o.w = (zv.w - mu) * rstd * lw.w + lb.w;
            store_a4(smem, r, lane, o);
        }
    }
    CP_WAIT(0);
    __syncthreads();                 // zn + Wq + Wk ready

    // ---------- fused q|k projections -> S -> softmax -> P fragments ----------
    uint32_t pf[2][4], plf[2][4];
    {
        float cq[4][4], ck[4][4];
        #pragma unroll
        for (int j = 0; j < 4; ++j)
            #pragma unroll
            for (int q = 0; q < 4; ++q) { cq[j][q] = 0.f; ck[j][q] = 0.f; }
        gemm_qk(base, wm, wn, lane, cq, ck);

        #pragma unroll
        for (int hh = 0; hh < 2; ++hh) {
            uint32_t qf[4], kf[4];
            qf[0] = h2bits(cq[2*hh][0],   cq[2*hh][1]);
            qf[1] = h2bits(cq[2*hh][2],   cq[2*hh][3]);
            qf[2] = h2bits(cq[2*hh+1][0], cq[2*hh+1][1]);
            qf[3] = h2bits(cq[2*hh+1][2], cq[2*hh+1][3]);
            kf[0] = h2bits(ck[2*hh][0],   ck[2*hh][1]);    // j0-7,  c0-7
            kf[1] = h2bits(ck[2*hh+1][0], ck[2*hh+1][1]);  // j0-7,  c8-15
            kf[2] = h2bits(ck[2*hh][2],   ck[2*hh][3]);    // j8-15, c0-7
            kf[3] = h2bits(ck[2*hh+1][2], ck[2*hh+1][3]);  // j8-15, c8-15

            float s0[4] = {0.f,0.f,0.f,0.f}, s1[4] = {0.f,0.f,0.f,0.f};
            mma_f16(s0, qf, &kf[0]);     // j 0-7
            mma_f16(s1, qf, &kf[2]);     // j 8-15
            #pragma unroll
            for (int q = 0; q < 4; ++q) { s0[q] *= 0.25f; s1[q] *= 0.25f; }

            float mlo = fmaxf(fmaxf(s0[0], s0[1]), fmaxf(s1[0], s1[1]));
            float mhi = fmaxf(fmaxf(s0[2], s0[3]), fmaxf(s1[2], s1[3]));
            mlo = fmaxf(mlo, __shfl_xor_sync(0xffffffffu, mlo, 1));
            mlo = fmaxf(mlo, __shfl_xor_sync(0xffffffffu, mlo, 2));
            mhi = fmaxf(mhi, __shfl_xor_sync(0xffffffffu, mhi, 1));
            mhi = fmaxf(mhi, __shfl_xor_sync(0xffffffffu, mhi, 2));
            s0[0] = __expf(s0[0] - mlo); s0[1] = __expf(s0[1] - mlo);
            s1[0] = __expf(s1[0] - mlo); s1[1] = __expf(s1[1] - mlo);
            s0[2] = __expf(s0[2] - mhi); s0[3] = __expf(s0[3] - mhi);
            s1[2] = __expf(s1[2] - mhi); s1[3] = __expf(s1[3] - mhi);
            float slo = s0[0] + s0[1] + s1[0] + s1[1];
            float shi = s0[2] + s0[3] + s1[2] + s1[3];
            slo += __shfl_xor_sync(0xffffffffu, slo, 1);
            slo += __shfl_xor_sync(0xffffffffu, slo, 2);
            shi += __shfl_xor_sync(0xffffffffu, shi, 1);
            shi += __shfl_xor_sync(0xffffffffu, shi, 2);
            const float ilo = 1.0f / slo, ihi = 1.0f / shi;
            s0[0] *= ilo; s0[1] *= ilo; s1[0] *= ilo; s1[1] *= ilo;
            s0[2] *= ihi; s0[3] *= ihi; s1[2] *= ihi; s1[3] *= ihi;

            pf[hh][0] = h2bits(s0[0], s0[1]);  plf[hh][0] = h2res(s0[0], s0[1], pf[hh][0]);
            pf[hh][1] = h2bits(s0[2], s0[3]);  plf[hh][1] = h2res(s0[2], s0[3], pf[hh][1]);
            pf[hh][2] = h2bits(s1[0], s1[1]);  plf[hh][2] = h2res(s1[0], s1[1], pf[hh][2]);
            pf[hh][3] = h2bits(s1[2], s1[3]);  plf[hh][3] = h2res(s1[2], s1[3], pf[hh][3]);
        }
    }
    __syncthreads();                 // B0/B1 reads done
    stage_img(base, SM_B0, wimg(2), t);   // Wv
    stage_img(base, SM_B1, wimg(3), t);   // Wg
    cp_commit();
    CP_WAIT(0);
    __syncthreads();                 // Wv + Wg ready

    // ---------- fused v(dual)|g projections -> O = P V -> gate ----------
    float oc[2][2][4];
    {
        float cv[4][4], cg[4][4];
        #pragma unroll
        for (int j = 0; j < 4; ++j)
            #pragma unroll
            for (int q = 0; q < 4; ++q) { cv[j][q] = 0.f; cg[j][q] = 0.f; }
        gemm_vg(base, wm, wn, lane, cv, cg);

        // O = P V via in-register transpose of v accumulators
        #pragma unroll
        for (int hh = 0; hh < 2; ++hh) {
            #pragma unroll
            for (int cb = 0; cb < 2; ++cb) {
                const int nb = hh * 2 + cb;
                const uint32_t m0 = h2bits(cv[nb][0], cv[nb][1]);
                const uint32_t m1 = h2bits(cv[nb][2], cv[nb][3]);
                const uint32_t r0 = h2res(cv[nb][0], cv[nb][1], m0);
                const uint32_t r1 = h2res(cv[nb][2], cv[nb][3], m1);
                uint32_t bh[2], bl[2];
                bh[0] = movm(m0); bh[1] = movm(m1);
                bl[0] = movm(r0); bl[1] = movm(r1);
                float* o = oc[hh][cb];
                o[0] = 0.f; o[1] = 0.f; o[2] = 0.f; o[3] = 0.f;
                mma_f16(o, pf[hh],  bh);
                mma_f16(o, plf[hh], bh);
                mma_f16(o, pf[hh],  bl);
            }
        }

        __syncthreads();             // all zn reads done; B0 (Wv) free
        stage_img(base, SM_B0, wimg(4), t);   // Wo
        cp_commit();

        // gate with sigmoid(cg + bg) and store o into A tiles
        #pragma unroll
        for (int hh = 0; hh < 2; ++hh) {
            #pragma unroll
            for (int cb = 0; cb < 2; ++cb) {
                const int nb = hh * 2 + cb;
                const int col = wn * 32 + nb * 8 + 2 * (lane & 3);
                const float b0 = bg[col], b1 = bg[col + 1];
                float* o = oc[hh][cb];
                o[0] *= sigmoidf_(cg[nb][0] + b0);
                o[1] *= sigmoidf_(cg[nb][1] + b1);
                o[2] *= sigmoidf_(cg[nb][2] + b0);
                o[3] *= sigmoidf_(cg[nb][3] + b1);
                const int r = wm * 16 + (lane >> 2);
                store_o2(smem, r,     col, o[0], o[1]);
                store_o2(smem, r + 8, col, o[2], o[3]);
            }
        }
    }
    CP_WAIT(0);
    __syncthreads();                 // o visible; Wo ready

    // ---------- out GEMM: o @ Wo + bo ----------
    {
        float c[4][4];
        #pragma unroll
        for (int j = 0; j < 4; ++j) { c[j][0]=0.f; c[j][1]=0.f; c[j][2]=0.f; c[j][3]=0.f; }
        gemm_dual(base, SM_B0, wm, wn, lane, c);

        const int r  = wm * 16 + (lane >> 2);
        const int r8 = r + 8;
        const long long grow  = (long long)(r  & 15) * PAIRS + pbase + (r  >> 4);
        const long long grow8 = (long long)(r8 & 15) * PAIRS + pbase + (r8 >> 4);
        #pragma unroll
        for (int nb = 0; nb < 4; ++nb) {
            const int col = wn * 32 + nb * 8 + 2 * (lane & 3);
            const float b0 = bo[col], b1 = bo[col + 1];
            *(float2*)&out[grow  * 128 + col] = make_float2(c[nb][0] + b0, c[nb][1] + b1);
            *(float2*)&out[grow8 * 128 + col] = make_float2(c[nb][2] + b0, c[nb][3] + b1);
        }
    }
}

// =====================================================================================
extern "C" void kernel_launch(void* const* d_in, const int* in_sizes, int n_in,
                              void* d_out, int out_size)
{
    (void)in_sizes; (void)n_in; (void)out_size;
    const float* z   = (const float*)d_in[0];
    const float* lnw = (const float*)d_in[1];
    const float* lnb = (const float*)d_in[2];
    const float* Wq  = (const float*)d_in[3];
    const float* Wk  = (const float*)d_in[4];
    const float* Wv  = (const float*)d_in[5];
    const float* Wg  = (const float*)d_in[6];
    const float* bg  = (const float*)d_in[7];
    const float* Wo  = (const float*)d_in[8];
    const float* bo  = (const float*)d_in[9];
    float* out = (float*)d_out;

    cudaFuncSetAttribute(kernel_fused, cudaFuncAttributeMaxDynamicSharedMemorySize, SMEM_TOTAL);

    kernel_prep<<<5, 256>>>(Wq, Wk, Wv, Wg, Wo);
    kernel_fused<<<PAIRS / 2, NT, SMEM_TOTAL>>>(z, lnw, lnb, bg, bo, out);
}

// round 11
// speedup vs baseline: 2.5511x; 1.0516x over previous
#include <cuda_runtime.h>
#include <cuda_fp16.h>
#include <cstdint>

#define PAIRS   16384
#define NBLOCKS 4096         // 16384 pairs / 4 per block-iteration
#define NT      512          // 16 warps, 1 CTA/SM (persistent)
#define GRID    152          // GB300 SM count

// ---------------- smem layout (bytes) ----------------
#define SM_A_HI  0u          // 64x128 fp16 swizzled (zn, later o_hi)
#define SM_A_LO  16384u      // zn_lo / o_lo
#define W_OFF(m) (32768u + (uint32_t)(m) * 32768u)   // 5 resident W images
#define SMEM_TOTAL 196608u

// ---------------- W images: 5 mats x 128x128 fp16, [n][k] ----------------
__device__ __half g_wimg[5 * 16384];

// ---------------- helpers ----------------
__device__ __forceinline__ uint32_t smem_u32(const void* p) {
    uint32_t a;
    asm("{ .reg .u64 t; cvta.to.shared.u64 t, %1; cvt.u32.u64 %0, t; }" : "=r"(a) : "l"(p));
    return a;
}
__device__ __forceinline__ float sigmoidf_(float x) { return 1.0f / (1.0f + __expf(-x)); }

__device__ __forceinline__ void ldmA4(uint32_t r[4], uint32_t addr) {
    asm volatile("ldmatrix.sync.aligned.m8n8.x4.shared.b16 {%0,%1,%2,%3}, [%4];"
                 : "=r"(r[0]), "=r"(r[1]), "=r"(r[2]), "=r"(r[3]) : "r"(addr));
}
__device__ __forceinline__ void ldmB2(uint32_t r[2], uint32_t addr) {
    asm volatile("ldmatrix.sync.aligned.m8n8.x2.shared.b16 {%0,%1}, [%2];"
                 : "=r"(r[0]), "=r"(r[1]) : "r"(addr));
}
__device__ __forceinline__ void mma_f16(float c[4], const uint32_t a[4], const uint32_t b[2]) {
    asm volatile(
        "mma.sync.aligned.m16n8k16.row.col.f32.f16.f16.f32 "
        "{%0,%1,%2,%3}, {%4,%5,%6,%7}, {%8,%9}, {%0,%1,%2,%3};"
        : "+f"(c[0]), "+f"(c[1]), "+f"(c[2]), "+f"(c[3])
        : "r"(a[0]), "r"(a[1]), "r"(a[2]), "r"(a[3]), "r"(b[0]), "r"(b[1]));
}
__device__ __forceinline__ uint32_t movm(uint32_t a) {
    uint32_t d;
    asm volatile("movmatrix.sync.aligned.m8n8.trans.b16 %0, %1;" : "=r"(d) : "r"(a));
    return d;
}
__device__ __forceinline__ void cp_async16(uint32_t dst, const void* src) {
    asm volatile("cp.async.ca.shared.global [%0], [%1], 16;" :: "r"(dst), "l"(src));
}
__device__ __forceinline__ void cp_commit() { asm volatile("cp.async.commit_group;"); }
#define CP_WAIT(n) asm volatile("cp.async.wait_group %0;" :: "n"(n))

__device__ __forceinline__ uint32_t h2bits(float x, float y) {
    __half2 h = __floats2half2_rn(x, y);
    return *(uint32_t*)&h;
}
__device__ __forceinline__ uint32_t h2res(float x, float y, uint32_t hb) {
    __half2 h = *(__half2*)&hb;
    float2 f = __half22float2(h);
    __half2 l = __floats2half2_rn(x - f.x, y - f.y);
    return *(uint32_t*)&l;
}

// =====================================================================================
// prep: round W to fp16, transpose to [n][k]
// =====================================================================================
__global__ void kernel_prep(const float* __restrict__ Wq, const float* __restrict__ Wk,
                            const float* __restrict__ Wv, const float* __restrict__ Wg,
                            const float* __restrict__ Wo)
{
    const int m = blockIdx.x;
    const float* W = (m == 0) ? Wq : (m == 1) ? Wk : (m == 2) ? Wv : (m == 3) ? Wg : Wo;
    __half* hi = g_wimg + (long long)m * 16384;
    for (int idx = threadIdx.x; idx < 16384; idx += blockDim.x) {
        const int n = idx >> 7, k = idx & 127;
        hi[n * 128 + k] = __float2half_rn(W[k * 128 + n]);
    }
}

// ---------------- building blocks ----------------
__device__ __forceinline__ void stage_img(uint32_t base, uint32_t dstOff,
                                          const __half* img, int t)
{
    #pragma unroll
    for (int it = 0; it < 4; ++it) {
        const int idx = t + it * NT;
        const uint32_t row = (uint32_t)(idx >> 4), c = (uint32_t)(idx & 15);
        cp_async16(base + dstOff + row * 256u + ((c ^ (row & 7u)) << 4),
                   img + row * 128u + c * 8u);
    }
}

// fused single+single: cq += Ah*B0, ck += Ah*B1 (shared A loads)
__device__ __forceinline__ void gemm_qk(uint32_t base, uint32_t b0Off, uint32_t b1Off,
                                        int wm, int wn, int lane,
                                        float cq[4][4], float ck[4][4])
{
    const uint32_t arow = (uint32_t)(wm * 16 + (lane & 15));
    const uint32_t asel = (uint32_t)(lane >> 4);
    const int brow0 = wn * 32 + (lane & 7);
    const uint32_t bsel = (uint32_t)((lane >> 3) & 1);
    #pragma unroll
    for (int k = 0; k < 8; ++k) {
        uint32_t ah[4], b0[4][2], b1[4][2];
        const uint32_t c16 = (uint32_t)(k * 2) + asel;
        ldmA4(ah, base + SM_A_HI + arow * 256u + ((c16 ^ (arow & 7u)) << 4));
        #pragma unroll
        for (int nb = 0; nb < 4; ++nb) {
            const uint32_t row = (uint32_t)(brow0 + nb * 8);
            const uint32_t bc = (uint32_t)(k * 2) + bsel;
            const uint32_t off = row * 256u + ((bc ^ (row & 7u)) << 4);
            ldmB2(b0[nb], base + b0Off + off);
            ldmB2(b1[nb], base + b1Off + off);
        }
        #pragma unroll
        for (int nb = 0; nb < 4; ++nb) {
            mma_f16(cq[nb], ah, b0[nb]);
            mma_f16(ck[nb], ah, b1[nb]);
        }
    }
}

// fused dual+single: cv += (Ah+Al)*B0, cg += Ah*B1 (shared A loads)
__device__ __forceinline__ void gemm_vg(uint32_t base, uint32_t b0Off, uint32_t b1Off,
                                        int wm, int wn, int lane,
                                        float cv[4][4], float cg[4][4])
{
    const uint32_t arow = (uint32_t)(wm * 16 + (lane & 15));
    const uint32_t asel = (uint32_t)(lane >> 4);
    const int brow0 = wn * 32 + (lane & 7);
    const uint32_t bsel = (uint32_t)((lane >> 3) & 1);
    #pragma unroll
    for (int k = 0; k < 8; ++k) {
        uint32_t ah[4], al[4], b0[4][2], b1[4][2];
        const uint32_t c16 = (uint32_t)(k * 2) + asel;
        const uint32_t ad = base + arow * 256u + ((c16 ^ (arow & 7u)) << 4);
        ldmA4(ah, ad + SM_A_HI);
        ldmA4(al, ad + SM_A_LO);
        #pragma unroll
        for (int nb = 0; nb < 4; ++nb) {
            const uint32_t row = (uint32_t)(brow0 + nb * 8);
            const uint32_t bc = (uint32_t)(k * 2) + bsel;
            const uint32_t off = row * 256u + ((bc ^ (row & 7u)) << 4);
            ldmB2(b0[nb], base + b0Off + off);
            ldmB2(b1[nb], base + b1Off + off);
        }
        #pragma unroll
        for (int nb = 0; nb < 4; ++nb) {
            mma_f16(cv[nb], ah, b0[nb]);
            mma_f16(cg[nb], ah, b1[nb]);
            mma_f16(cv[nb], al, b0[nb]);
        }
    }
}

// dual pass for out GEMM: c += (Ah+Al)*B
__device__ __forceinline__ void gemm_dual(uint32_t base, uint32_t bOff, int wm, int wn,
                                          int lane, float c[4][4])
{
    const uint32_t arow = (uint32_t)(wm * 16 + (lane & 15));
    const uint32_t asel = (uint32_t)(lane >> 4);
    const int brow0 = wn * 32 + (lane & 7);
    const uint32_t bsel = (uint32_t)((lane >> 3) & 1);
    #pragma unroll
    for (int k = 0; k < 8; ++k) {
        uint32_t ah[4], al[4], b[4][2];
        const uint32_t c16 = (uint32_t)(k * 2) + asel;
        const uint32_t ad = base + arow * 256u + ((c16 ^ (arow & 7u)) << 4);
        ldmA4(ah, ad + SM_A_HI);
        ldmA4(al, ad + SM_A_LO);
        #pragma unroll
        for (int nb = 0; nb < 4; ++nb) {
            const uint32_t row = (uint32_t)(brow0 + nb * 8);
            const uint32_t bc = (uint32_t)(k * 2) + bsel;
            ldmB2(b[nb], base + bOff + row * 256u + ((bc ^ (row & 7u)) << 4));
        }
        #pragma unroll
        for (int nb = 0; nb < 4; ++nb) {
            mma_f16(c[nb], ah, b[nb]);
            mma_f16(c[nb], al, b[nb]);
        }
    }
}

// LN: split 4 floats -> hi/lo fp16 into swizzled A tiles
__device__ __forceinline__ void store_a4(char* smem, int r, int lane, float4 v)
{
    const uint32_t chunk = (uint32_t)(lane >> 1);
    const uint32_t addr = (uint32_t)r * 256u + ((chunk ^ (uint32_t)(r & 7)) << 4)
                        + (uint32_t)((lane & 1) * 8);
    const __half hx = __float2half_rn(v.x), hy = __float2half_rn(v.y);
    const __half hz = __float2half_rn(v.z), hw = __float2half_rn(v.w);
    const __half2 h01 = __halves2half2(hx, hy), h23 = __halves2half2(hz, hw);
    const __half2 l01 = __halves2half2(__float2half_rn(v.x - __half2float(hx)),
                                       __float2half_rn(v.y - __half2float(hy)));
    const __half2 l23 = __halves2half2(__float2half_rn(v.z - __half2float(hz)),
                                       __float2half_rn(v.w - __half2float(hw)));
    *(__half2*)(smem + SM_A_HI + addr)     = h01;
    *(__half2*)(smem + SM_A_HI + addr + 4) = h23;
    *(__half2*)(smem + SM_A_LO + addr)     = l01;
    *(__half2*)(smem + SM_A_LO + addr + 4) = l23;
}

// hi/lo split store of one half2 into the A tiles
__device__ __forceinline__ void store_o2(char* smem, int row, int col, float x, float y)
{
    const uint32_t chunk = (uint32_t)(col >> 3);
    const uint32_t off = (uint32_t)row * 256u + ((chunk ^ (uint32_t)(row & 7)) << 4)
                       + (uint32_t)((col & 7) * 2);
    const __half2 h = __floats2half2_rn(x, y);
    const float2 f = __half22float2(h);
    const __half2 l = __floats2half2_rn(x - f.x, y - f.y);
    *(__half2*)(smem + SM_A_HI + off) = h;
    *(__half2*)(smem + SM_A_LO + off) = l;
}

__device__ __forceinline__ const __half* wimg(int mat) {
    return g_wimg + (long long)mat * 16384;
}

// =====================================================================================
// persistent fused kernel: all 5 W images resident in smem; loop over pair-blocks.
// 4 pairs per iteration, 16 warps; warp (wm=pair, wn=head-pair)
// =====================================================================================
__global__ __launch_bounds__(NT, 1)
void kernel_fused(const float* __restrict__ z,
                  const float* __restrict__ lnw, const float* __restrict__ lnb,
                  const float* __restrict__ bg,  const float* __restrict__ bo,
                  float* __restrict__ out)
{
    extern __shared__ char smem[];
    const uint32_t base = smem_u32(smem);

    const int t = threadIdx.x, lane = t & 31, warp = t >> 5;
    const int wm = warp >> 2, wn = warp & 3;

    // ---------- stage all 5 W images once ----------
    #pragma unroll
    for (int m = 0; m < 5; ++m)
        stage_img(base, W_OFF(m), wimg(m), t);
    cp_commit();

    const float4 lw = *(const float4*)&lnw[lane * 4];
    const float4 lb = *(const float4*)&lnb[lane * 4];

    for (int blk = blockIdx.x; blk < NBLOCKS; blk += gridDim.x) {
        const int pbase = blk * 4;
        __syncthreads();             // prior iteration's A reads done

        // ---------- LayerNorm -> zn hi/lo (64 rows) ----------
        for (int r = warp; r < 64; r += 16) {
            const long long grow = (long long)(r & 15) * PAIRS + pbase + (r >> 4);
            const float4 zv = *(const float4*)&z[grow * 128 + lane * 4];
            float s  = zv.x + zv.y + zv.z + zv.w;
            float s2 = zv.x*zv.x + zv.y*zv.y + zv.z*zv.z + zv.w*zv.w;
            #pragma unroll
            for (int off = 16; off > 0; off >>= 1) {
                s  += __shfl_xor_sync(0xffffffffu, s,  off);
                s2 += __shfl_xor_sync(0xffffffffu, s2, off);
            }
            const float mu   = s * (1.0f / 128.0f);
            const float var  = s2 * (1.0f / 128.0f) - mu * mu;
            const float rstd = rsqrtf(var + 1e-5f);
            float4 o;
            o.x = (zv.x - mu) * rstd * lw.x + lb.x;
            o.y = (zv.y - mu) * rstd * lw.y + lb.y;
            o.z = (zv.z - mu) * rstd * lw.z + lb.z;
            o.w = (zv.w - mu) * rstd * lw.w + lb.w;
            store_a4(smem, r, lane, o);
        }
        CP_WAIT(0);                  // no-op after first iteration
        __syncthreads();             // zn (+W on iter 0) ready

        // ---------- fused q|k -> S -> softmax -> P fragments ----------
        uint32_t pf[2][4], plf[2][4];
        {
            float cq[4][4], ck[4][4];
            #pragma unroll
            for (int j = 0; j < 4; ++j)
                #pragma unroll
                for (int q = 0; q < 4; ++q) { cq[j][q] = 0.f; ck[j][q] = 0.f; }
            gemm_qk(base, W_OFF(0), W_OFF(1), wm, wn, lane, cq, ck);

            #pragma unroll
            for (int hh = 0; hh < 2; ++hh) {
                uint32_t qf[4], kf[4];
                qf[0] = h2bits(cq[2*hh][0],   cq[2*hh][1]);
                qf[1] = h2bits(cq[2*hh][2],   cq[2*hh][3]);
                qf[2] = h2bits(cq[2*hh+1][0], cq[2*hh+1][1]);
                qf[3] = h2bits(cq[2*hh+1][2], cq[2*hh+1][3]);
                kf[0] = h2bits(ck[2*hh][0],   ck[2*hh][1]);
                kf[1] = h2bits(ck[2*hh+1][0], ck[2*hh+1][1]);
                kf[2] = h2bits(ck[2*hh][2],   ck[2*hh][3]);
                kf[3] = h2bits(ck[2*hh+1][2], ck[2*hh+1][3]);

                float s0[4] = {0.f,0.f,0.f,0.f}, s1[4] = {0.f,0.f,0.f,0.f};
                mma_f16(s0, qf, &kf[0]);
                mma_f16(s1, qf, &kf[2]);
                #pragma unroll
                for (int q = 0; q < 4; ++q) { s0[q] *= 0.25f; s1[q] *= 0.25f; }

                float mlo = fmaxf(fmaxf(s0[0], s0[1]), fmaxf(s1[0], s1[1]));
                float mhi = fmaxf(fmaxf(s0[2], s0[3]), fmaxf(s1[2], s1[3]));
                mlo = fmaxf(mlo, __shfl_xor_sync(0xffffffffu, mlo, 1));
                mlo = fmaxf(mlo, __shfl_xor_sync(0xffffffffu, mlo, 2));
                mhi = fmaxf(mhi, __shfl_xor_sync(0xffffffffu, mhi, 1));
                mhi = fmaxf(mhi, __shfl_xor_sync(0xffffffffu, mhi, 2));
                s0[0] = __expf(s0[0] - mlo); s0[1] = __expf(s0[1] - mlo);
                s1[0] = __expf(s1[0] - mlo); s1[1] = __expf(s1[1] - mlo);
                s0[2] = __expf(s0[2] - mhi); s0[3] = __expf(s0[3] - mhi);
                s1[2] = __expf(s1[2] - mhi); s1[3] = __expf(s1[3] - mhi);
                float slo = s0[0] + s0[1] + s1[0] + s1[1];
                float shi = s0[2] + s0[3] + s1[2] + s1[3];
                slo += __shfl_xor_sync(0xffffffffu, slo, 1);
                slo += __shfl_xor_sync(0xffffffffu, slo, 2);
                shi += __shfl_xor_sync(0xffffffffu, shi, 1);
                shi += __shfl_xor_sync(0xffffffffu, shi, 2);
                const float ilo = 1.0f / slo, ihi = 1.0f / shi;
                s0[0] *= ilo; s0[1] *= ilo; s1[0] *= ilo; s1[1] *= ilo;
                s0[2] *= ihi; s0[3] *= ihi; s1[2] *= ihi; s1[3] *= ihi;

                pf[hh][0] = h2bits(s0[0], s0[1]);  plf[hh][0] = h2res(s0[0], s0[1], pf[hh][0]);
                pf[hh][1] = h2bits(s0[2], s0[3]);  plf[hh][1] = h2res(s0[2], s0[3], pf[hh][1]);
                pf[hh][2] = h2bits(s1[0], s1[1]);  plf[hh][2] = h2res(s1[0], s1[1], pf[hh][2]);
                pf[hh][3] = h2bits(s1[2], s1[3]);  plf[hh][3] = h2res(s1[2], s1[3], pf[hh][3]);
            }
        }

        // ---------- fused v(dual)|g -> O = P V -> gate -> store o ----------
        float oc[2][2][4];
        {
            float cv[4][4], cg[4][4];
            #pragma unroll
            for (int j = 0; j < 4; ++j)
                #pragma unroll
                for (int q = 0; q < 4; ++q) { cv[j][q] = 0.f; cg[j][q] = 0.f; }
            gemm_vg(base, W_OFF(2), W_OFF(3), wm, wn, lane, cv, cg);

            #pragma unroll
            for (int hh = 0; hh < 2; ++hh) {
                #pragma unroll
                for (int cb = 0; cb < 2; ++cb) {
                    const int nb = hh * 2 + cb;
                    const uint32_t m0 = h2bits(cv[nb][0], cv[nb][1]);
                    const uint32_t m1 = h2bits(cv[nb][2], cv[nb][3]);
                    const uint32_t r0 = h2res(cv[nb][0], cv[nb][1], m0);
                    const uint32_t r1 = h2res(cv[nb][2], cv[nb][3], m1);
                    uint32_t bh[2], bl[2];
                    bh[0] = movm(m0); bh[1] = movm(m1);
                    bl[0] = movm(r0); bl[1] = movm(r1);
                    float* o = oc[hh][cb];
                    o[0] = 0.f; o[1] = 0.f; o[2] = 0.f; o[3] = 0.f;
                    mma_f16(o, pf[hh],  bh);
                    mma_f16(o, plf[hh], bh);
                    mma_f16(o, pf[hh],  bl);
                }
            }

            __syncthreads();         // all zn reads done; A tiles free for o

            #pragma unroll
            for (int hh = 0; hh < 2; ++hh) {
                #pragma unroll
                for (int cb = 0; cb < 2; ++cb) {
                    const int nb = hh * 2 + cb;
                    const int col = wn * 32 + nb * 8 + 2 * (lane & 3);
                    const float b0 = bg[col], b1 = bg[col + 1];
                    float* o = oc[hh][cb];
                    o[0] *= sigmoidf_(cg[nb][0] + b0);
                    o[1] *= sigmoidf_(cg[nb][1] + b1);
                    o[2] *= sigmoidf_(cg[nb][2] + b0);
                    o[3] *= sigmoidf_(cg[nb][3] + b1);
                    const int r = wm * 16 + (lane >> 2);
                    store_o2(smem, r,     col, o[0], o[1]);
                    store_o2(smem, r + 8, col, o[2], o[3]);
                }
            }
        }
        __syncthreads();             // o visible

        // ---------- out GEMM: o @ Wo + bo ----------
        {
            float c[4][4];
            #pragma unroll
            for (int j = 0; j < 4; ++j) { c[j][0]=0.f; c[j][1]=0.f; c[j][2]=0.f; c[j][3]=0.f; }
            gemm_dual(base, W_OFF(4), wm, wn, lane, c);

            const int r  = wm * 16 + (lane >> 2);
            const int r8 = r + 8;
            const long long grow  = (long long)(r  & 15) * PAIRS + pbase + (r  >> 4);
            const long long grow8 = (long long)(r8 & 15) * PAIRS + pbase + (r8 >> 4);
            #pragma unroll
            for (int nb = 0; nb < 4; ++nb) {
                const int col = wn * 32 + nb * 8 + 2 * (lane & 3);
                const float b0 = bo[col], b1 = bo[col + 1];
                *(float2*)&out[grow  * 128 + col] = make_float2(c[nb][0] + b0, c[nb][1] + b1);
                *(float2*)&out[grow8 * 128 + col] = make_float2(c[nb][2] + b0, c[nb][3] + b1);
            }
        }
    }
}

// =====================================================================================
extern "C" void kernel_launch(void* const* d_in, const int* in_sizes, int n_in,
                              void* d_out, int out_size)
{
    (void)in_sizes; (void)n_in; (void)out_size;
    const float* z   = (const float*)d_in[0];
    const float* lnw = (const float*)d_in[1];
    const float* lnb = (const float*)d_in[2];
    const float* Wq  = (const float*)d_in[3];
    const float* Wk  = (const float*)d_in[4];
    const float* Wv  = (const float*)d_in[5];
    const float* Wg  = (const float*)d_in[6];
    const float* bg  = (const float*)d_in[7];
    const float* Wo  = (const float*)d_in[8];
    const float* bo  = (const float*)d_in[9];
    float* out = (float*)d_out;

    cudaFuncSetAttribute(kernel_fused, cudaFuncAttributeMaxDynamicSharedMemorySize, SMEM_TOTAL);

    kernel_prep<<<5, 256>>>(Wq, Wk, Wv, Wg, Wo);
    kernel_fused<<<GRID, NT, SMEM_TOTAL>>>(z, lnw, lnb, bg, bo, out);
}